// round 3
// baseline (speedup 1.0000x reference)
#include <cuda_runtime.h>
#include <math.h>

#define Bb 8
#define Nn 4096
#define Dd 256
#define Hh 256

// ---------------- static device scratch (allocation-free) ----------------
__device__ float g_Q[(size_t)Bb * Nn * Hh];           // 33.5 MB
__device__ float g_K[(size_t)Bb * Nn * Hh];           // 33.5 MB
__device__ float g_V[(size_t)Bb * Nn * Hh];           // 33.5 MB
__device__ float g_S[(size_t)Bb * Nn * Nn];           // 536 MB score scratch
__device__ float g_m[Bb * Nn];                        // row max
__device__ float g_c[Bb * Nn];                        // 1/Z per row
__device__ float g_w[Bb * Nn];                        // column weights

// ---------------- kernel 0: zero accumulators ----------------
__global__ void zero_kernel(float* __restrict__ out) {
    int i = blockIdx.x * 256 + threadIdx.x;
    if (i < Bb * Nn) g_w[i] = 0.0f;
    if (i < Bb * Hh) out[i] = 0.0f;
}

// ---------------- kernel 1: QKV projection GEMM ----------------
// out[r][h] = sum_d x[r][d] * W[d][h] + b[h]   for r in [0, B*N)
// grid: (rows/64, H/64, 3)   block: 256
__global__ __launch_bounds__(256) void qkv_kernel(
    const float* __restrict__ x,
    const float* __restrict__ Wq, const float* __restrict__ bq,
    const float* __restrict__ Wk, const float* __restrict__ bk,
    const float* __restrict__ Wv, const float* __restrict__ bv)
{
    const float* W; const float* bias; float* out;
    if (blockIdx.z == 0)      { W = Wq; bias = bq; out = g_Q; }
    else if (blockIdx.z == 1) { W = Wk; bias = bk; out = g_K; }
    else                      { W = Wv; bias = bv; out = g_V; }

    const int r0 = blockIdx.x * 64;
    const int h0 = blockIdx.y * 64;
    const int tid = threadIdx.x;
    const int tx = tid & 15, ty = tid >> 4;

    __shared__ float As[32][68];   // [d][r] (transposed), stride 68 -> 272B (16B-aligned rows)
    __shared__ float Ws[32][68];   // [d][h]

    float acc[4][4] = {};

    for (int dk = 0; dk < Dd; dk += 32) {
        // x tile: 64 rows x 32 d, transposed into As[d][r]
        #pragma unroll
        for (int i = 0; i < 2; i++) {
            int f  = tid + 256 * i;        // 0..511 float4s
            int r  = f >> 3;
            int c4 = (f & 7) * 4;
            float4 v = *reinterpret_cast<const float4*>(&x[(size_t)(r0 + r) * Dd + dk + c4]);
            As[c4 + 0][r] = v.x; As[c4 + 1][r] = v.y;
            As[c4 + 2][r] = v.z; As[c4 + 3][r] = v.w;
        }
        // W tile: 32 d x 64 h, natural layout Ws[d][h]
        #pragma unroll
        for (int i = 0; i < 2; i++) {
            int f  = tid + 256 * i;
            int d  = f >> 4;
            int c4 = (f & 15) * 4;
            float4 v = *reinterpret_cast<const float4*>(&W[(size_t)(dk + d) * Hh + h0 + c4]);
            *reinterpret_cast<float4*>(&Ws[d][c4]) = v;
        }
        __syncthreads();
        #pragma unroll
        for (int kk = 0; kk < 32; kk++) {
            float4 a  = *reinterpret_cast<const float4*>(&As[kk][ty * 4]);
            float4 w4 = *reinterpret_cast<const float4*>(&Ws[kk][tx * 4]);
            float av[4] = {a.x, a.y, a.z, a.w};
            float wv[4] = {w4.x, w4.y, w4.z, w4.w};
            #pragma unroll
            for (int i = 0; i < 4; i++)
                #pragma unroll
                for (int j = 0; j < 4; j++)
                    acc[i][j] += av[i] * wv[j];
        }
        __syncthreads();
    }

    float bj[4];
    #pragma unroll
    for (int j = 0; j < 4; j++) bj[j] = bias[h0 + tx * 4 + j];
    #pragma unroll
    for (int i = 0; i < 4; i++) {
        size_t row = (size_t)(r0 + ty * 4 + i);
        #pragma unroll
        for (int j = 0; j < 4; j++)
            out[row * Hh + h0 + tx * 4 + j] = acc[i][j] + bj[j];
    }
}

// ---------------- kernel 2: S = Q @ K^T * scale ----------------
// grid: (N/64 k-tiles, N/64 q-tiles, B)   block: 256
__global__ __launch_bounds__(256) void scores_kernel() {
    const int b  = blockIdx.z;
    const int q0 = blockIdx.y * 64;
    const int k0 = blockIdx.x * 64;
    const float* Q = g_Q + (size_t)b * Nn * Hh;
    const float* K = g_K + (size_t)b * Nn * Hh;

    const int tid = threadIdx.x;
    const int tx = tid & 15, ty = tid >> 4;

    __shared__ float Qs[32][68];   // [d][q]
    __shared__ float Ks[32][68];   // [d][k]

    float acc[4][4] = {};

    for (int dk = 0; dk < Hh; dk += 32) {
        #pragma unroll
        for (int i = 0; i < 2; i++) {
            int f  = tid + 256 * i;
            int r  = f >> 3;
            int c4 = (f & 7) * 4;
            float4 v = *reinterpret_cast<const float4*>(&Q[(size_t)(q0 + r) * Hh + dk + c4]);
            Qs[c4 + 0][r] = v.x; Qs[c4 + 1][r] = v.y;
            Qs[c4 + 2][r] = v.z; Qs[c4 + 3][r] = v.w;
        }
        #pragma unroll
        for (int i = 0; i < 2; i++) {
            int f  = tid + 256 * i;
            int r  = f >> 3;
            int c4 = (f & 7) * 4;
            float4 v = *reinterpret_cast<const float4*>(&K[(size_t)(k0 + r) * Hh + dk + c4]);
            Ks[c4 + 0][r] = v.x; Ks[c4 + 1][r] = v.y;
            Ks[c4 + 2][r] = v.z; Ks[c4 + 3][r] = v.w;
        }
        __syncthreads();
        #pragma unroll
        for (int kk = 0; kk < 32; kk++) {
            float4 a  = *reinterpret_cast<const float4*>(&Qs[kk][ty * 4]);
            float4 b4 = *reinterpret_cast<const float4*>(&Ks[kk][tx * 4]);
            float av[4] = {a.x, a.y, a.z, a.w};
            float bv[4] = {b4.x, b4.y, b4.z, b4.w};
            #pragma unroll
            for (int i = 0; i < 4; i++)
                #pragma unroll
                for (int j = 0; j < 4; j++)
                    acc[i][j] += av[i] * bv[j];
        }
        __syncthreads();
    }

    const float scale = 0.0625f;   // 1/sqrt(256)
    #pragma unroll
    for (int i = 0; i < 4; i++) {
        size_t row = (size_t)(b * Nn + q0 + ty * 4 + i);
        #pragma unroll
        for (int j = 0; j < 4; j++)
            g_S[row * Nn + k0 + tx * 4 + j] = acc[i][j] * scale;
    }
}

// ---------------- kernel 3: per-row softmax stats (m, 1/Z) ----------------
// grid: B*N blocks of 128 threads, one row each
__global__ __launch_bounds__(128) void rowstats_kernel() {
    const int row = blockIdx.x;
    const float4* S4 = reinterpret_cast<const float4*>(g_S + (size_t)row * Nn);

    float m = -1e30f, s = 0.0f;
    #pragma unroll 4
    for (int k4 = threadIdx.x; k4 < Nn / 4; k4 += 128) {
        float4 v = S4[k4];
        float vm = fmaxf(fmaxf(v.x, v.y), fmaxf(v.z, v.w));
        if (vm > m) { s *= __expf(m - vm); m = vm; }
        s += __expf(v.x - m) + __expf(v.y - m) + __expf(v.z - m) + __expf(v.w - m);
    }

    __shared__ float sm[128], ss[128];
    sm[threadIdx.x] = m; ss[threadIdx.x] = s;
    __syncthreads();
    for (int off = 64; off > 0; off >>= 1) {
        if (threadIdx.x < off) {
            float m1 = sm[threadIdx.x],       s1 = ss[threadIdx.x];
            float m2 = sm[threadIdx.x + off], s2 = ss[threadIdx.x + off];
            float M = fmaxf(m1, m2);
            sm[threadIdx.x] = M;
            ss[threadIdx.x] = s1 * __expf(m1 - M) + s2 * __expf(m2 - M);
        }
        __syncthreads();
    }
    if (threadIdx.x == 0) {
        g_m[row] = sm[0];
        g_c[row] = 1.0f / ss[0];
    }
}

// ---------------- kernel 4: column weights w[b,k] = sum_q p[q,k] ----------------
// grid: (N/128, N/256, B)   block: 128 (one k per thread)
__global__ __launch_bounds__(128) void colsum_kernel() {
    const int b  = blockIdx.z;
    const int k  = blockIdx.x * 128 + threadIdx.x;
    const int q0 = blockIdx.y * 256;
    const float* Sb = g_S + (size_t)b * Nn * Nn;

    float acc = 0.0f;
    #pragma unroll 4
    for (int q = q0; q < q0 + 256; q++) {
        float mq = g_m[b * Nn + q];
        float cq = g_c[b * Nn + q];
        float v  = Sb[(size_t)q * Nn + k];
        acc += __expf(v - mq) * cq;
    }
    atomicAdd(&g_w[b * Nn + k], acc);
}

// ---------------- kernel 5: out[b,h] = (1/N) sum_k w[b,k] V[b,k,h] ----------------
// grid: (B, 16 k-splits)   block: 256 (one h per thread)
__global__ __launch_bounds__(256) void out_kernel(float* __restrict__ out) {
    const int b  = blockIdx.x;
    const int ks = blockIdx.y;
    const int h  = threadIdx.x;
    const float* Vb = g_V + (size_t)b * Nn * Hh;

    float acc = 0.0f;
    #pragma unroll 8
    for (int k = ks * 256; k < ks * 256 + 256; k++)
        acc += g_w[b * Nn + k] * Vb[(size_t)k * Hh + h];

    atomicAdd(&out[b * Hh + h], acc * (1.0f / Nn));
}

// ---------------- launch ----------------
extern "C" void kernel_launch(void* const* d_in, const int* in_sizes, int n_in,
                              void* d_out, int out_size) {
    const float* x  = (const float*)d_in[0];
    const float* Wq = (const float*)d_in[1];
    const float* bq = (const float*)d_in[2];
    const float* Wk = (const float*)d_in[3];
    const float* bk = (const float*)d_in[4];
    const float* Wv = (const float*)d_in[5];
    const float* bv = (const float*)d_in[6];
    float* out = (float*)d_out;

    zero_kernel<<<128, 256>>>(out);
    qkv_kernel<<<dim3((Bb * Nn) / 64, Hh / 64, 3), 256>>>(x, Wq, bq, Wk, bk, Wv, bv);
    scores_kernel<<<dim3(Nn / 64, Nn / 64, Bb), 256>>>();
    rowstats_kernel<<<Bb * Nn, 128>>>();
    colsum_kernel<<<dim3(Nn / 128, Nn / 256, Bb), 128>>>();
    out_kernel<<<dim3(Bb, 16), 256>>>(out);
}

// round 6
// speedup vs baseline: 2.2951x; 2.2951x over previous
#include <cuda_runtime.h>
#include <math.h>
#include <stdint.h>

#define Bb 8
#define Nn 4096
#define Dd 256
#define Hh 256

// ---------------- static device scratch (allocation-free) ----------------
__device__ float g_Q[(size_t)Bb * Nn * Hh];           // 33.5 MB
__device__ float g_K[(size_t)Bb * Nn * Hh];           // 33.5 MB
__device__ float g_V[(size_t)Bb * Nn * Hh];           // 33.5 MB
__device__ float g_S[(size_t)Bb * Nn * Nn];           // 536 MB score scratch
__device__ float g_m[Bb * Nn];                        // row max
__device__ float g_c[Bb * Nn];                        // 1/Z per row
__device__ float g_w[Bb * Nn];                        // column weights

// ================= helpers =================
__device__ __forceinline__ uint32_t smem_u32(const void* p) {
    uint32_t a;
    asm("{ .reg .u64 t; cvta.to.shared.u64 t, %1; cvt.u32.u64 %0, t; }" : "=r"(a) : "l"(p));
    return a;
}
__device__ __forceinline__ uint32_t f2tf32(float f) {
    uint32_t u;
    asm("cvt.rna.tf32.f32 %0, %1;" : "=r"(u) : "f"(f));
    return u;
}
__device__ __forceinline__ void sts128(uint32_t addr, uint32_t a, uint32_t b, uint32_t c, uint32_t d) {
    asm volatile("st.shared.v4.b32 [%0], {%1,%2,%3,%4};" :: "r"(addr), "r"(a), "r"(b), "r"(c), "r"(d) : "memory");
}
__device__ __forceinline__ uint32_t lds32(uint32_t addr) {
    uint32_t v;
    asm volatile("ld.shared.b32 %0, [%1];" : "=r"(v) : "r"(addr));
    return v;
}
// m16n8k8 tf32 MMA, fp32 accumulate (sm_80+ path; lands on tensor pipe)
__device__ __forceinline__ void mma_tf32(float* c,
                                         uint32_t a0, uint32_t a1, uint32_t a2, uint32_t a3,
                                         uint32_t b0, uint32_t b1) {
    asm volatile(
        "mma.sync.aligned.m16n8k8.row.col.f32.tf32.tf32.f32 "
        "{%0,%1,%2,%3}, {%4,%5,%6,%7}, {%8,%9}, {%0,%1,%2,%3};"
        : "+f"(c[0]), "+f"(c[1]), "+f"(c[2]), "+f"(c[3])
        : "r"(a0), "r"(a1), "r"(a2), "r"(a3), "r"(b0), "r"(b1));
}
#define SW128(o) ((o) ^ (((o) >> 3) & 0x70u))

// ---------------- kernel 0: zero accumulators ----------------
__global__ void zero_kernel(float* __restrict__ out) {
    int i = blockIdx.x * 256 + threadIdx.x;
    if (i < Bb * Nn) g_w[i] = 0.0f;
    if (i < Bb * Hh) out[i] = 0.0f;
}

// ---------------- kernel 1: QKV projection GEMM (FFMA fp32) ----------------
__global__ __launch_bounds__(256) void qkv_kernel(
    const float* __restrict__ x,
    const float* __restrict__ Wq, const float* __restrict__ bq,
    const float* __restrict__ Wk, const float* __restrict__ bk,
    const float* __restrict__ Wv, const float* __restrict__ bv)
{
    const float* W; const float* bias; float* out;
    if (blockIdx.z == 0)      { W = Wq; bias = bq; out = g_Q; }
    else if (blockIdx.z == 1) { W = Wk; bias = bk; out = g_K; }
    else                      { W = Wv; bias = bv; out = g_V; }

    const int r0 = blockIdx.x * 64;
    const int h0 = blockIdx.y * 64;
    const int tid = threadIdx.x;
    const int tx = tid & 15, ty = tid >> 4;

    __shared__ float As[32][68];
    __shared__ float Ws[32][68];

    float acc[4][4] = {};

    for (int dk = 0; dk < Dd; dk += 32) {
        #pragma unroll
        for (int i = 0; i < 2; i++) {
            int f  = tid + 256 * i;
            int r  = f >> 3;
            int c4 = (f & 7) * 4;
            float4 v = *reinterpret_cast<const float4*>(&x[(size_t)(r0 + r) * Dd + dk + c4]);
            As[c4 + 0][r] = v.x; As[c4 + 1][r] = v.y;
            As[c4 + 2][r] = v.z; As[c4 + 3][r] = v.w;
        }
        #pragma unroll
        for (int i = 0; i < 2; i++) {
            int f  = tid + 256 * i;
            int d  = f >> 4;
            int c4 = (f & 15) * 4;
            float4 v = *reinterpret_cast<const float4*>(&W[(size_t)(dk + d) * Hh + h0 + c4]);
            *reinterpret_cast<float4*>(&Ws[d][c4]) = v;
        }
        __syncthreads();
        #pragma unroll
        for (int kk = 0; kk < 32; kk++) {
            float4 a  = *reinterpret_cast<const float4*>(&As[kk][ty * 4]);
            float4 w4 = *reinterpret_cast<const float4*>(&Ws[kk][tx * 4]);
            float av[4] = {a.x, a.y, a.z, a.w};
            float wv[4] = {w4.x, w4.y, w4.z, w4.w};
            #pragma unroll
            for (int i = 0; i < 4; i++)
                #pragma unroll
                for (int j = 0; j < 4; j++)
                    acc[i][j] += av[i] * wv[j];
        }
        __syncthreads();
    }

    float bj[4];
    #pragma unroll
    for (int j = 0; j < 4; j++) bj[j] = bias[h0 + tx * 4 + j];
    #pragma unroll
    for (int i = 0; i < 4; i++) {
        size_t row = (size_t)(r0 + ty * 4 + i);
        #pragma unroll
        for (int j = 0; j < 4; j++)
            out[row * Hh + h0 + tx * 4 + j] = acc[i][j] + bj[j];
    }
}

// ---------------- kernel 2: S = Q @ K^T * scale  (mma.sync tf32) ----------------
// CTA tile 128(q) x 128(k), K=256 in 8 chunks of 32 floats.
// 8 warps, each 64x32 (4 m16-tiles x 4 n8-tiles), m16n8k8 tf32 MMA.
// SMEM rows are 128B; SW128 float-swizzle makes all fragment LDS conflict-free.
// grid: (N/128, N/128, B)  block: 256
__global__ __launch_bounds__(256) void scores_mma_kernel() {
    __shared__ float Qs[128 * 32];
    __shared__ float Ks[128 * 32];

    const int tid  = threadIdx.x;
    const int wid  = tid >> 5;
    const int lane = tid & 31;
    const int g = lane >> 2, t = lane & 3;
    const int wm = (wid & 1) * 64;        // warp m offset
    const int wn = (wid >> 1) * 32;       // warp n offset

    const int b  = blockIdx.z;
    const int q0 = blockIdx.y * 128;
    const int k0 = blockIdx.x * 128;
    const float* Q  = g_Q + (size_t)b * Nn * Hh + (size_t)q0 * Hh;
    const float* Kp = g_K + (size_t)b * Nn * Hh + (size_t)k0 * Hh;

    const uint32_t sQ = smem_u32(Qs);
    const uint32_t sK = smem_u32(Ks);

    // global-load indexing: 1024 float4 per matrix per chunk, 4 per thread
    const int lr = tid >> 3;              // row 0..31 (+32*i)
    const int lc = tid & 7;               // float4 col 0..7
    // swizzled STS byte offset within tile for (row = lr+32*i, col4 = lc)
    uint32_t stsOff[4];
    #pragma unroll
    for (int i = 0; i < 4; i++)
        stsOff[i] = SW128((uint32_t)((lr + 32 * i) * 128 + lc * 16));

    // fragment base addresses (row&7 == g for all fragment rows)
    const uint32_t aBase = sQ + (uint32_t)(wm + g) * 128;
    const uint32_t bBase = sK + (uint32_t)(wn + g) * 128;
    const uint32_t swz   = (uint32_t)g << 4;

    float c[4][4][4];
    #pragma unroll
    for (int mt = 0; mt < 4; mt++)
        #pragma unroll
        for (int nt = 0; nt < 4; nt++)
            #pragma unroll
            for (int r = 0; r < 4; r++)
                c[mt][nt][r] = 0.0f;

    float4 pfA[4], pfB[4];
    #pragma unroll
    for (int i = 0; i < 4; i++) {
        pfA[i] = *reinterpret_cast<const float4*>(&Q [(size_t)(lr + 32 * i) * Hh + lc * 4]);
        pfB[i] = *reinterpret_cast<const float4*>(&Kp[(size_t)(lr + 32 * i) * Hh + lc * 4]);
    }

    for (int ch = 0; ch < 8; ch++) {
        __syncthreads();   // previous chunk's reads finished
        #pragma unroll
        for (int i = 0; i < 4; i++) {
            sts128(sQ + stsOff[i], f2tf32(pfA[i].x), f2tf32(pfA[i].y), f2tf32(pfA[i].z), f2tf32(pfA[i].w));
            sts128(sK + stsOff[i], f2tf32(pfB[i].x), f2tf32(pfB[i].y), f2tf32(pfB[i].z), f2tf32(pfB[i].w));
        }
        __syncthreads();

        if (ch < 7) {
            const int nc = (ch + 1) * 32;
            #pragma unroll
            for (int i = 0; i < 4; i++) {
                pfA[i] = *reinterpret_cast<const float4*>(&Q [(size_t)(lr + 32 * i) * Hh + nc + lc * 4]);
                pfB[i] = *reinterpret_cast<const float4*>(&Kp[(size_t)(lr + 32 * i) * Hh + nc + lc * 4]);
            }
        }

        #pragma unroll
        for (int ks = 0; ks < 4; ks++) {
            const uint32_t ct0 = (uint32_t)((ks * 8 + t)     << 2) ^ swz;
            const uint32_t ct1 = (uint32_t)((ks * 8 + t + 4) << 2) ^ swz;
            uint32_t b0[4], b1[4];
            #pragma unroll
            for (int nt = 0; nt < 4; nt++) {
                b0[nt] = lds32(bBase + nt * 1024 + ct0);
                b1[nt] = lds32(bBase + nt * 1024 + ct1);
            }
            #pragma unroll
            for (int mt = 0; mt < 4; mt++) {
                uint32_t a0 = lds32(aBase + mt * 2048 +        ct0);
                uint32_t a1 = lds32(aBase + mt * 2048 + 1024 + ct0);
                uint32_t a2 = lds32(aBase + mt * 2048 +        ct1);
                uint32_t a3 = lds32(aBase + mt * 2048 + 1024 + ct1);
                #pragma unroll
                for (int nt = 0; nt < 4; nt++)
                    mma_tf32(c[mt][nt], a0, a1, a2, a3, b0[nt], b1[nt]);
            }
        }
    }

    const float scale = 0.0625f;    // 1/sqrt(256)
    #pragma unroll
    for (int mt = 0; mt < 4; mt++) {
        const int row = q0 + wm + mt * 16 + g;
        #pragma unroll
        for (int nt = 0; nt < 4; nt++) {
            const int col = k0 + wn + nt * 8 + 2 * t;
            float2 v0, v1;
            v0.x = c[mt][nt][0] * scale; v0.y = c[mt][nt][1] * scale;
            v1.x = c[mt][nt][2] * scale; v1.y = c[mt][nt][3] * scale;
            *reinterpret_cast<float2*>(&g_S[(size_t)(b * Nn + row)     * Nn + col]) = v0;
            *reinterpret_cast<float2*>(&g_S[(size_t)(b * Nn + row + 8) * Nn + col]) = v1;
        }
    }
}

// ---------------- kernel 3: per-row softmax stats (m, 1/Z) ----------------
__global__ __launch_bounds__(128) void rowstats_kernel() {
    const int row = blockIdx.x;
    const float4* S4 = reinterpret_cast<const float4*>(g_S + (size_t)row * Nn);

    float m = -1e30f, s = 0.0f;
    #pragma unroll 4
    for (int k4 = threadIdx.x; k4 < Nn / 4; k4 += 128) {
        float4 v = S4[k4];
        float vm = fmaxf(fmaxf(v.x, v.y), fmaxf(v.z, v.w));
        if (vm > m) { s *= __expf(m - vm); m = vm; }
        s += __expf(v.x - m) + __expf(v.y - m) + __expf(v.z - m) + __expf(v.w - m);
    }

    __shared__ float sm[128], ss[128];
    sm[threadIdx.x] = m; ss[threadIdx.x] = s;
    __syncthreads();
    for (int off = 64; off > 0; off >>= 1) {
        if (threadIdx.x < off) {
            float m1 = sm[threadIdx.x],       s1 = ss[threadIdx.x];
            float m2 = sm[threadIdx.x + off], s2 = ss[threadIdx.x + off];
            float M = fmaxf(m1, m2);
            sm[threadIdx.x] = M;
            ss[threadIdx.x] = s1 * __expf(m1 - M) + s2 * __expf(m2 - M);
        }
        __syncthreads();
    }
    if (threadIdx.x == 0) {
        g_m[row] = sm[0];
        g_c[row] = 1.0f / ss[0];
    }
}

// ---------------- kernel 4: column weights w[b,k] = sum_q p[q,k] ----------------
__global__ __launch_bounds__(128) void colsum_kernel() {
    const int b  = blockIdx.z;
    const int k  = blockIdx.x * 128 + threadIdx.x;
    const int q0 = blockIdx.y * 256;
    const float* Sb = g_S + (size_t)b * Nn * Nn;

    float acc = 0.0f;
    #pragma unroll 4
    for (int q = q0; q < q0 + 256; q++) {
        float mq = g_m[b * Nn + q];
        float cq = g_c[b * Nn + q];
        float v  = Sb[(size_t)q * Nn + k];
        acc += __expf(v - mq) * cq;
    }
    atomicAdd(&g_w[b * Nn + k], acc);
}

// ---------------- kernel 5: out[b,h] = (1/N) sum_k w[b,k] V[b,k,h] ----------------
__global__ __launch_bounds__(256) void out_kernel(float* __restrict__ out) {
    const int b  = blockIdx.x;
    const int ks = blockIdx.y;
    const int h  = threadIdx.x;
    const float* Vb = g_V + (size_t)b * Nn * Hh;

    float acc = 0.0f;
    #pragma unroll 8
    for (int k = ks * 256; k < ks * 256 + 256; k++)
        acc += g_w[b * Nn + k] * Vb[(size_t)k * Hh + h];

    atomicAdd(&out[b * Hh + h], acc * (1.0f / Nn));
}

// ---------------- launch ----------------
extern "C" void kernel_launch(void* const* d_in, const int* in_sizes, int n_in,
                              void* d_out, int out_size) {
    const float* x  = (const float*)d_in[0];
    const float* Wq = (const float*)d_in[1];
    const float* bq = (const float*)d_in[2];
    const float* Wk = (const float*)d_in[3];
    const float* bk = (const float*)d_in[4];
    const float* Wv = (const float*)d_in[5];
    const float* bv = (const float*)d_in[6];
    float* out = (float*)d_out;

    zero_kernel<<<128, 256>>>(out);
    qkv_kernel<<<dim3((Bb * Nn) / 64, Hh / 64, 3), 256>>>(x, Wq, bq, Wk, bk, Wv, bv);
    scores_mma_kernel<<<dim3(Nn / 128, Nn / 128, Bb), 256>>>();
    rowstats_kernel<<<Bb * Nn, 128>>>();
    colsum_kernel<<<dim3(Nn / 128, Nn / 256, Bb), 128>>>();
    out_kernel<<<dim3(Bb, 16), 256>>>(out);
}

// round 7
// speedup vs baseline: 3.1982x; 1.3935x over previous
#include <cuda_runtime.h>
#include <cuda_bf16.h>
#include <math.h>
#include <stdint.h>

#define Bb 8
#define Nn 4096
#define Dd 256
#define Hh 256

// ---------------- static device scratch (allocation-free) ----------------
__device__ float g_Q[(size_t)Bb * Nn * Hh];              // 33.5 MB
__device__ float g_K[(size_t)Bb * Nn * Hh];              // 33.5 MB
__device__ float g_V[(size_t)Bb * Nn * Hh];              // 33.5 MB
__device__ __nv_bfloat16 g_P[(size_t)Bb * Nn * Nn];      // 268 MB: P = exp(S)
__device__ float g_Wt[3 * Dd * Hh];                      // W^T for Q,K,V
__device__ float g_z[Bb * Nn];                           // row sums Z
__device__ float g_c[Bb * Nn];                           // 1/Z
__device__ float g_w[Bb * Nn];                           // column weights

// ================= helpers =================
__device__ __forceinline__ uint32_t smem_u32(const void* p) {
    uint32_t a;
    asm("{ .reg .u64 t; cvta.to.shared.u64 t, %1; cvt.u32.u64 %0, t; }" : "=r"(a) : "l"(p));
    return a;
}
__device__ __forceinline__ uint32_t f2tf32(float f) {
    uint32_t u;
    asm("cvt.rna.tf32.f32 %0, %1;" : "=r"(u) : "f"(f));
    return u;
}
__device__ __forceinline__ void sts128(uint32_t addr, uint32_t a, uint32_t b, uint32_t c, uint32_t d) {
    asm volatile("st.shared.v4.b32 [%0], {%1,%2,%3,%4};" :: "r"(addr), "r"(a), "r"(b), "r"(c), "r"(d) : "memory");
}
__device__ __forceinline__ uint32_t lds32(uint32_t addr) {
    uint32_t v;
    asm volatile("ld.shared.b32 %0, [%1];" : "=r"(v) : "r"(addr));
    return v;
}
__device__ __forceinline__ void mma_tf32(float* c,
                                         uint32_t a0, uint32_t a1, uint32_t a2, uint32_t a3,
                                         uint32_t b0, uint32_t b1) {
    asm volatile(
        "mma.sync.aligned.m16n8k8.row.col.f32.tf32.tf32.f32 "
        "{%0,%1,%2,%3}, {%4,%5,%6,%7}, {%8,%9}, {%0,%1,%2,%3};"
        : "+f"(c[0]), "+f"(c[1]), "+f"(c[2]), "+f"(c[3])
        : "r"(a0), "r"(a1), "r"(a2), "r"(a3), "r"(b0), "r"(b1));
}
#define SW128(o) ((o) ^ (((o) >> 3) & 0x70u))

// ---------------- kernel 0: zero accumulators ----------------
__global__ void zero_kernel(float* __restrict__ out) {
    int i = blockIdx.x * 256 + threadIdx.x;
    if (i < Bb * Nn) { g_w[i] = 0.0f; g_z[i] = 0.0f; }
    if (i < Bb * Hh) out[i] = 0.0f;
}

// ---------------- kernel 1: W transpose (768 KB, trivial) ----------------
__global__ void transpose_w_kernel(const float* __restrict__ Wq,
                                   const float* __restrict__ Wk,
                                   const float* __restrict__ Wv) {
    const float* W = (blockIdx.z == 0) ? Wq : (blockIdx.z == 1) ? Wk : Wv;
    float* Wt = g_Wt + blockIdx.z * (Dd * Hh);
    __shared__ float t[32][33];
    const int x0 = blockIdx.x * 32, y0 = blockIdx.y * 32;
    #pragma unroll
    for (int i = threadIdx.y; i < 32; i += 8)
        t[i][threadIdx.x] = W[(size_t)(y0 + i) * Hh + x0 + threadIdx.x];   // t[d][h] local
    __syncthreads();
    #pragma unroll
    for (int i = threadIdx.y; i < 32; i += 8)
        Wt[(size_t)(x0 + i) * Dd + y0 + threadIdx.x] = t[threadIdx.x][i];  // Wt[h][d]
}

// ---------------- kernel 2: QKV projection via mma.sync tf32 ----------------
// out[r][h] = x[r][:] . Wt[h][:] + bias[h].  CTA tile 128(r) x 128(h), K=256.
// Identical fragment/pipeline structure to the proven scores MMA kernel.
// grid: (Hh/128, (B*N)/128, 3)  block: 256
__global__ __launch_bounds__(256) void qkv_mma_kernel(
    const float* __restrict__ x,
    const float* __restrict__ bq, const float* __restrict__ bk, const float* __restrict__ bv)
{
    __shared__ float Qs[128 * 32];
    __shared__ float Ks[128 * 32];

    const int tid  = threadIdx.x;
    const int wid  = tid >> 5;
    const int lane = tid & 31;
    const int g = lane >> 2, t = lane & 3;
    const int wm = (wid & 1) * 64;
    const int wn = (wid >> 1) * 32;

    const int z  = blockIdx.z;
    const float* bias = (z == 0) ? bq : (z == 1) ? bk : bv;
    float* out = (z == 0) ? g_Q : (z == 1) ? g_K : g_V;

    const int r0 = blockIdx.y * 128;
    const int h0 = blockIdx.x * 128;
    const float* A  = x + (size_t)r0 * Dd;
    const float* Bm = g_Wt + z * (Dd * Hh) + (size_t)h0 * Dd;

    const uint32_t sQ = smem_u32(Qs);
    const uint32_t sK = smem_u32(Ks);

    const int lr = tid >> 3;
    const int lc = tid & 7;
    uint32_t stsOff[4];
    #pragma unroll
    for (int i = 0; i < 4; i++)
        stsOff[i] = SW128((uint32_t)((lr + 32 * i) * 128 + lc * 16));

    const uint32_t aBase = sQ + (uint32_t)(wm + g) * 128;
    const uint32_t bBase = sK + (uint32_t)(wn + g) * 128;
    const uint32_t swz   = (uint32_t)g << 4;

    float c[4][4][4];
    #pragma unroll
    for (int mt = 0; mt < 4; mt++)
        #pragma unroll
        for (int nt = 0; nt < 4; nt++)
            #pragma unroll
            for (int r = 0; r < 4; r++)
                c[mt][nt][r] = 0.0f;

    float4 pfA[4], pfB[4];
    #pragma unroll
    for (int i = 0; i < 4; i++) {
        pfA[i] = *reinterpret_cast<const float4*>(&A [(size_t)(lr + 32 * i) * Dd + lc * 4]);
        pfB[i] = *reinterpret_cast<const float4*>(&Bm[(size_t)(lr + 32 * i) * Dd + lc * 4]);
    }

    for (int ch = 0; ch < 8; ch++) {
        __syncthreads();
        #pragma unroll
        for (int i = 0; i < 4; i++) {
            sts128(sQ + stsOff[i], f2tf32(pfA[i].x), f2tf32(pfA[i].y), f2tf32(pfA[i].z), f2tf32(pfA[i].w));
            sts128(sK + stsOff[i], f2tf32(pfB[i].x), f2tf32(pfB[i].y), f2tf32(pfB[i].z), f2tf32(pfB[i].w));
        }
        __syncthreads();

        if (ch < 7) {
            const int nc = (ch + 1) * 32;
            #pragma unroll
            for (int i = 0; i < 4; i++) {
                pfA[i] = *reinterpret_cast<const float4*>(&A [(size_t)(lr + 32 * i) * Dd + nc + lc * 4]);
                pfB[i] = *reinterpret_cast<const float4*>(&Bm[(size_t)(lr + 32 * i) * Dd + nc + lc * 4]);
            }
        }

        #pragma unroll
        for (int ks = 0; ks < 4; ks++) {
            const uint32_t ct0 = (uint32_t)((ks * 8 + t)     << 2) ^ swz;
            const uint32_t ct1 = (uint32_t)((ks * 8 + t + 4) << 2) ^ swz;
            uint32_t b0[4], b1[4];
            #pragma unroll
            for (int nt = 0; nt < 4; nt++) {
                b0[nt] = lds32(bBase + nt * 1024 + ct0);
                b1[nt] = lds32(bBase + nt * 1024 + ct1);
            }
            #pragma unroll
            for (int mt = 0; mt < 4; mt++) {
                uint32_t a0 = lds32(aBase + mt * 2048 +        ct0);
                uint32_t a1 = lds32(aBase + mt * 2048 + 1024 + ct0);
                uint32_t a2 = lds32(aBase + mt * 2048 +        ct1);
                uint32_t a3 = lds32(aBase + mt * 2048 + 1024 + ct1);
                #pragma unroll
                for (int nt = 0; nt < 4; nt++)
                    mma_tf32(c[mt][nt], a0, a1, a2, a3, b0[nt], b1[nt]);
            }
        }
    }

    #pragma unroll
    for (int mt = 0; mt < 4; mt++) {
        const int row = r0 + wm + mt * 16 + g;
        #pragma unroll
        for (int nt = 0; nt < 4; nt++) {
            const int col = h0 + wn + nt * 8 + 2 * t;
            float2 bc = *reinterpret_cast<const float2*>(&bias[col]);
            float2 v0, v1;
            v0.x = c[mt][nt][0] + bc.x; v0.y = c[mt][nt][1] + bc.y;
            v1.x = c[mt][nt][2] + bc.x; v1.y = c[mt][nt][3] + bc.y;
            *reinterpret_cast<float2*>(&out[(size_t)row       * Hh + col]) = v0;
            *reinterpret_cast<float2*>(&out[(size_t)(row + 8) * Hh + col]) = v1;
        }
    }
}

// ---------------- kernel 3: P = exp(Q K^T * scale), Z row-sums (fused) ----------------
// Unsafe softmax (no max pass): scores are O(1) here, exp cannot overflow fp32.
// grid: (N/128 k-tiles, N/128 q-tiles, B)  block: 256
__global__ __launch_bounds__(256) void scores_fused_kernel() {
    __shared__ float Qs[128 * 32];
    __shared__ float Ks[128 * 32];
    __shared__ float rsum[128];

    const int tid  = threadIdx.x;
    const int wid  = tid >> 5;
    const int lane = tid & 31;
    const int g = lane >> 2, t = lane & 3;
    const int wm = (wid & 1) * 64;
    const int wn = (wid >> 1) * 32;

    const int b  = blockIdx.z;
    const int q0 = blockIdx.y * 128;
    const int k0 = blockIdx.x * 128;
    const float* Q  = g_Q + (size_t)b * Nn * Hh + (size_t)q0 * Hh;
    const float* Kp = g_K + (size_t)b * Nn * Hh + (size_t)k0 * Hh;

    const uint32_t sQ = smem_u32(Qs);
    const uint32_t sK = smem_u32(Ks);

    const int lr = tid >> 3;
    const int lc = tid & 7;
    uint32_t stsOff[4];
    #pragma unroll
    for (int i = 0; i < 4; i++)
        stsOff[i] = SW128((uint32_t)((lr + 32 * i) * 128 + lc * 16));

    const uint32_t aBase = sQ + (uint32_t)(wm + g) * 128;
    const uint32_t bBase = sK + (uint32_t)(wn + g) * 128;
    const uint32_t swz   = (uint32_t)g << 4;

    float c[4][4][4];
    #pragma unroll
    for (int mt = 0; mt < 4; mt++)
        #pragma unroll
        for (int nt = 0; nt < 4; nt++)
            #pragma unroll
            for (int r = 0; r < 4; r++)
                c[mt][nt][r] = 0.0f;

    float4 pfA[4], pfB[4];
    #pragma unroll
    for (int i = 0; i < 4; i++) {
        pfA[i] = *reinterpret_cast<const float4*>(&Q [(size_t)(lr + 32 * i) * Hh + lc * 4]);
        pfB[i] = *reinterpret_cast<const float4*>(&Kp[(size_t)(lr + 32 * i) * Hh + lc * 4]);
    }

    for (int ch = 0; ch < 8; ch++) {
        __syncthreads();
        #pragma unroll
        for (int i = 0; i < 4; i++) {
            sts128(sQ + stsOff[i], f2tf32(pfA[i].x), f2tf32(pfA[i].y), f2tf32(pfA[i].z), f2tf32(pfA[i].w));
            sts128(sK + stsOff[i], f2tf32(pfB[i].x), f2tf32(pfB[i].y), f2tf32(pfB[i].z), f2tf32(pfB[i].w));
        }
        __syncthreads();

        if (ch < 7) {
            const int nc = (ch + 1) * 32;
            #pragma unroll
            for (int i = 0; i < 4; i++) {
                pfA[i] = *reinterpret_cast<const float4*>(&Q [(size_t)(lr + 32 * i) * Hh + nc + lc * 4]);
                pfB[i] = *reinterpret_cast<const float4*>(&Kp[(size_t)(lr + 32 * i) * Hh + nc + lc * 4]);
            }
        }

        #pragma unroll
        for (int ks = 0; ks < 4; ks++) {
            const uint32_t ct0 = (uint32_t)((ks * 8 + t)     << 2) ^ swz;
            const uint32_t ct1 = (uint32_t)((ks * 8 + t + 4) << 2) ^ swz;
            uint32_t b0[4], b1[4];
            #pragma unroll
            for (int nt = 0; nt < 4; nt++) {
                b0[nt] = lds32(bBase + nt * 1024 + ct0);
                b1[nt] = lds32(bBase + nt * 1024 + ct1);
            }
            #pragma unroll
            for (int mt = 0; mt < 4; mt++) {
                uint32_t a0 = lds32(aBase + mt * 2048 +        ct0);
                uint32_t a1 = lds32(aBase + mt * 2048 + 1024 + ct0);
                uint32_t a2 = lds32(aBase + mt * 2048 +        ct1);
                uint32_t a3 = lds32(aBase + mt * 2048 + 1024 + ct1);
                #pragma unroll
                for (int nt = 0; nt < 4; nt++)
                    mma_tf32(c[mt][nt], a0, a1, a2, a3, b0[nt], b1[nt]);
            }
        }
    }

    // ---- fused epilogue: exp, bf16 store, per-row Z partial sums ----
    __syncthreads();
    if (tid < 128) rsum[tid] = 0.0f;
    __syncthreads();

    const float scale = 0.0625f;    // 1/sqrt(256)
    __nv_bfloat16* Pb = g_P + (size_t)(b * Nn) * Nn;

    #pragma unroll
    for (int mt = 0; mt < 4; mt++) {
        const int row = wm + mt * 16 + g;   // CTA-local row
        float s0 = 0.0f, s1 = 0.0f;
        #pragma unroll
        for (int nt = 0; nt < 4; nt++) {
            const int col = k0 + wn + nt * 8 + 2 * t;
            float e0 = __expf(c[mt][nt][0] * scale);
            float e1 = __expf(c[mt][nt][1] * scale);
            float e2 = __expf(c[mt][nt][2] * scale);
            float e3 = __expf(c[mt][nt][3] * scale);
            s0 += e0 + e1;
            s1 += e2 + e3;
            *reinterpret_cast<__nv_bfloat162*>(&Pb[(size_t)(q0 + row)     * Nn + col]) =
                __floats2bfloat162_rn(e0, e1);
            *reinterpret_cast<__nv_bfloat162*>(&Pb[(size_t)(q0 + row + 8) * Nn + col]) =
                __floats2bfloat162_rn(e2, e3);
        }
        // reduce across the 4 lanes of the quad (t = 0..3, same g)
        s0 += __shfl_xor_sync(0xFFFFFFFFu, s0, 1);
        s0 += __shfl_xor_sync(0xFFFFFFFFu, s0, 2);
        s1 += __shfl_xor_sync(0xFFFFFFFFu, s1, 1);
        s1 += __shfl_xor_sync(0xFFFFFFFFu, s1, 2);
        if (t == 0) {
            atomicAdd(&rsum[row],     s0);
            atomicAdd(&rsum[row + 8], s1);
        }
    }
    __syncthreads();
    if (tid < 128) atomicAdd(&g_z[b * Nn + q0 + tid], rsum[tid]);
}

// ---------------- kernel 4: invZ ----------------
__global__ void invz_kernel() {
    int i = blockIdx.x * 256 + threadIdx.x;
    g_c[i] = 1.0f / g_z[i];
}

// ---------------- kernel 5: w[b,k] = sum_q P[q,k] * invZ[q] ----------------
// grid: (N/256 k-pairs, N/256 q-chunks, B)  block: 128 (one bf16x2 pair per thread)
__global__ __launch_bounds__(128) void colsum_kernel() {
    const int b  = blockIdx.z;
    const int k2 = blockIdx.x * 128 + threadIdx.x;   // pair index
    const int q0 = blockIdx.y * 256;

    __shared__ float iz[256];
    if (threadIdx.x < 128) {
        iz[threadIdx.x]       = g_c[b * Nn + q0 + threadIdx.x];
        iz[threadIdx.x + 128] = g_c[b * Nn + q0 + 128 + threadIdx.x];
    }
    __syncthreads();

    const __nv_bfloat162* Pb = reinterpret_cast<const __nv_bfloat162*>(g_P + (size_t)(b * Nn) * Nn);

    float ax = 0.0f, ay = 0.0f;
    #pragma unroll 4
    for (int q = 0; q < 256; q++) {
        float2 v = __bfloat1622float2(Pb[(size_t)(q0 + q) * (Nn / 2) + k2]);
        float w = iz[q];
        ax += v.x * w;
        ay += v.y * w;
    }
    atomicAdd(&g_w[b * Nn + 2 * k2],     ax);
    atomicAdd(&g_w[b * Nn + 2 * k2 + 1], ay);
}

// ---------------- kernel 6: out[b,h] = (1/N) sum_k w[b,k] V[b,k,h] ----------------
__global__ __launch_bounds__(256) void out_kernel(float* __restrict__ out) {
    const int b  = blockIdx.x;
    const int ks = blockIdx.y;
    const int h  = threadIdx.x;
    const float* Vb = g_V + (size_t)b * Nn * Hh;

    float acc = 0.0f;
    #pragma unroll 8
    for (int k = ks * 256; k < ks * 256 + 256; k++)
        acc += g_w[b * Nn + k] * Vb[(size_t)k * Hh + h];

    atomicAdd(&out[b * Hh + h], acc * (1.0f / Nn));
}

// ---------------- launch ----------------
extern "C" void kernel_launch(void* const* d_in, const int* in_sizes, int n_in,
                              void* d_out, int out_size) {
    const float* x  = (const float*)d_in[0];
    const float* Wq = (const float*)d_in[1];
    const float* bq = (const float*)d_in[2];
    const float* Wk = (const float*)d_in[3];
    const float* bk = (const float*)d_in[4];
    const float* Wv = (const float*)d_in[5];
    const float* bv = (const float*)d_in[6];
    float* out = (float*)d_out;

    zero_kernel<<<128, 256>>>(out);
    transpose_w_kernel<<<dim3(8, 8, 3), dim3(32, 8)>>>(Wq, Wk, Wv);
    qkv_mma_kernel<<<dim3(Hh / 128, (Bb * Nn) / 128, 3), 256>>>(x, bq, bk, bv);
    scores_fused_kernel<<<dim3(Nn / 128, Nn / 128, Bb), 256>>>();
    invz_kernel<<<128, 256>>>();
    colsum_kernel<<<dim3(Nn / 256, Nn / 256, Bb), 128>>>();
    out_kernel<<<dim3(Bb, 16), 256>>>(out);
}

// round 8
// speedup vs baseline: 4.0194x; 1.2567x over previous
#include <cuda_runtime.h>
#include <cuda_bf16.h>
#include <math.h>
#include <stdint.h>

#define Bb 8
#define Nn 4096
#define Dd 256
#define Hh 256

// ---------------- static device scratch (allocation-free) ----------------
__device__ float g_Q[(size_t)Bb * Nn * Hh];              // 33.5 MB
__device__ float g_K[(size_t)Bb * Nn * Hh];              // 33.5 MB
__device__ float g_V[(size_t)Bb * Nn * Hh];              // 33.5 MB
__device__ __nv_bfloat16 g_P[(size_t)Bb * Nn * Nn];      // 268 MB: P = exp(S)
__device__ float g_Wt[3 * Dd * Hh];                      // W^T for Q,K,V
__device__ float g_z[Bb * Nn];                           // row sums Z
__device__ float g_c[Bb * Nn];                           // 1/Z
__device__ float g_w[Bb * Nn];                           // column weights

// ================= helpers =================
__device__ __forceinline__ uint32_t smem_u32(const void* p) {
    uint32_t a;
    asm("{ .reg .u64 t; cvta.to.shared.u64 t, %1; cvt.u32.u64 %0, t; }" : "=r"(a) : "l"(p));
    return a;
}
__device__ __forceinline__ uint32_t lds32(uint32_t addr) {
    uint32_t v;
    asm volatile("ld.shared.b32 %0, [%1];" : "=r"(v) : "r"(addr));
    return v;
}
__device__ __forceinline__ void cpasync16(uint32_t dst, const float* src) {
    asm volatile("cp.async.ca.shared.global [%0], [%1], 16;" :: "r"(dst), "l"(src));
}
#define CP_COMMIT() asm volatile("cp.async.commit_group;" ::: "memory")
#define CP_WAIT(N)  asm volatile("cp.async.wait_group %0;" :: "n"(N) : "memory")

__device__ __forceinline__ void mma_tf32(float* c,
                                         uint32_t a0, uint32_t a1, uint32_t a2, uint32_t a3,
                                         uint32_t b0, uint32_t b1) {
    asm volatile(
        "mma.sync.aligned.m16n8k8.row.col.f32.tf32.tf32.f32 "
        "{%0,%1,%2,%3}, {%4,%5,%6,%7}, {%8,%9}, {%0,%1,%2,%3};"
        : "+f"(c[0]), "+f"(c[1]), "+f"(c[2]), "+f"(c[3])
        : "r"(a0), "r"(a1), "r"(a2), "r"(a3), "r"(b0), "r"(b1));
}
#define SW128(o) ((o) ^ (((o) >> 3) & 0x70u))

#define MM_DYN_SMEM 65536   // 2 buffers x (Q 16KB + K 16KB)

// ---------------- kernel 0: zero accumulators ----------------
__global__ void zero_kernel(float* __restrict__ out) {
    int i = blockIdx.x * 256 + threadIdx.x;
    if (i < Bb * Nn) { g_w[i] = 0.0f; g_z[i] = 0.0f; }
    if (i < Bb * Hh) out[i] = 0.0f;
}

// ---------------- kernel 1: W transpose (768 KB, trivial) ----------------
__global__ void transpose_w_kernel(const float* __restrict__ Wq,
                                   const float* __restrict__ Wk,
                                   const float* __restrict__ Wv) {
    const float* W = (blockIdx.z == 0) ? Wq : (blockIdx.z == 1) ? Wk : Wv;
    float* Wt = g_Wt + blockIdx.z * (Dd * Hh);
    __shared__ float t[32][33];
    const int x0 = blockIdx.x * 32, y0 = blockIdx.y * 32;
    #pragma unroll
    for (int i = threadIdx.y; i < 32; i += 8)
        t[i][threadIdx.x] = W[(size_t)(y0 + i) * Hh + x0 + threadIdx.x];
    __syncthreads();
    #pragma unroll
    for (int i = threadIdx.y; i < 32; i += 8)
        Wt[(size_t)(x0 + i) * Dd + y0 + threadIdx.x] = t[threadIdx.x][i];
}

// ===== shared MMA mainloop (cp.async double-buffered, 128x128 tile, K=256) =====
// A rows from 'Ap' (stride 256), B rows from 'Bp' (stride 256); both K-major.
// Accumulators c[4][4][4] for a 64x32 warp tile; 8 warps cover 128x128.
struct MmaCtx {
    uint32_t aBase, bBase, swz;
    uint32_t stsOffQ[4], stsOffK[4];
    const float* Aq;   // per-thread gmem base for A
    const float* Bk;   // per-thread gmem base for B
};

__device__ __forceinline__ void mm_issue(const MmaCtx& cx, uint32_t sb, int ch, int buf) {
    const uint32_t bq = sb + (uint32_t)buf * 32768u;
    const uint32_t bk = bq + 16384u;
    const float* qa = cx.Aq + ch * 32;
    const float* ka = cx.Bk + ch * 32;
    #pragma unroll
    for (int i = 0; i < 4; i++) {
        cpasync16(bq + cx.stsOffQ[i], qa + (size_t)i * 32 * 256);
        cpasync16(bk + cx.stsOffK[i], ka + (size_t)i * 32 * 256);
    }
    CP_COMMIT();
}

__device__ __forceinline__ void mm_compute(const MmaCtx& cx, uint32_t sb, int buf,
                                           float c[4][4][4], int t) {
    const uint32_t off = (uint32_t)buf * 32768u;
    const uint32_t aB = cx.aBase + off;
    const uint32_t bB = cx.bBase + off + 16384u;
    #pragma unroll
    for (int ks = 0; ks < 4; ks++) {
        const uint32_t ct0 = (uint32_t)((ks * 8 + t)     << 2) ^ cx.swz;
        const uint32_t ct1 = (uint32_t)((ks * 8 + t + 4) << 2) ^ cx.swz;
        uint32_t b0[4], b1[4];
        #pragma unroll
        for (int nt = 0; nt < 4; nt++) {
            b0[nt] = lds32(bB + nt * 1024 + ct0);
            b1[nt] = lds32(bB + nt * 1024 + ct1);
        }
        #pragma unroll
        for (int mt = 0; mt < 4; mt++) {
            uint32_t a0 = lds32(aB + mt * 2048 +        ct0);
            uint32_t a1 = lds32(aB + mt * 2048 + 1024 + ct0);
            uint32_t a2 = lds32(aB + mt * 2048 +        ct1);
            uint32_t a3 = lds32(aB + mt * 2048 + 1024 + ct1);
            #pragma unroll
            for (int nt = 0; nt < 4; nt++)
                mma_tf32(c[mt][nt], a0, a1, a2, a3, b0[nt], b1[nt]);
        }
    }
}

#define MM_PROLOGUE(Aptr, Bptr)                                                  \
    extern __shared__ float dynsm[];                                             \
    const uint32_t sb = smem_u32(dynsm);                                         \
    const int tid  = threadIdx.x;                                                \
    const int wid  = tid >> 5;                                                   \
    const int lane = tid & 31;                                                   \
    const int g = lane >> 2, t = lane & 3;                                       \
    const int wm = (wid & 1) * 64;                                               \
    const int wn = (wid >> 1) * 32;                                              \
    const int lr = tid >> 3;                                                     \
    const int lc = tid & 7;                                                      \
    MmaCtx cx;                                                                   \
    _Pragma("unroll")                                                            \
    for (int i = 0; i < 4; i++) {                                                \
        uint32_t o = SW128((uint32_t)((lr + 32 * i) * 128 + lc * 16));           \
        cx.stsOffQ[i] = o; cx.stsOffK[i] = o;                                    \
    }                                                                            \
    cx.aBase = (uint32_t)(wm + g) * 128;                                         \
    cx.bBase = (uint32_t)(wn + g) * 128;                                         \
    cx.swz   = (uint32_t)g << 4;                                                 \
    cx.Aq = (Aptr) + (size_t)lr * 256 + lc * 4;                                  \
    cx.Bk = (Bptr) + (size_t)lr * 256 + lc * 4;                                  \
    cx.aBase += sb; cx.bBase += sb;                                              \
    float c[4][4][4];                                                            \
    _Pragma("unroll")                                                            \
    for (int mt = 0; mt < 4; mt++)                                               \
        _Pragma("unroll")                                                        \
        for (int nt = 0; nt < 4; nt++)                                           \
            _Pragma("unroll")                                                    \
            for (int r = 0; r < 4; r++)                                          \
                c[mt][nt][r] = 0.0f;                                             \
    mm_issue(cx, sb, 0, 0);                                                      \
    mm_issue(cx, sb, 1, 1);                                                      \
    _Pragma("unroll 1")                                                          \
    for (int ch = 0; ch < 8; ch++) {                                             \
        if (ch == 7) { CP_WAIT(0); } else { CP_WAIT(1); }                        \
        __syncthreads();                                                         \
        mm_compute(cx, sb, ch & 1, c, t);                                        \
        __syncthreads();                                                         \
        if (ch + 2 < 8) mm_issue(cx, sb, ch + 2, ch & 1);                        \
    }

// ---------------- kernel 2: QKV projection via mma.sync tf32 ----------------
// grid: (Hh/128, (B*N)/128, 3)  block: 256
__global__ __launch_bounds__(256, 2) void qkv_mma_kernel(
    const float* __restrict__ x,
    const float* __restrict__ bq, const float* __restrict__ bk, const float* __restrict__ bv)
{
    const int z  = blockIdx.z;
    const float* bias = (z == 0) ? bq : (z == 1) ? bk : bv;
    float* out = (z == 0) ? g_Q : (z == 1) ? g_K : g_V;
    const int r0 = blockIdx.y * 128;
    const int h0 = blockIdx.x * 128;
    const float* Aptr = x + (size_t)r0 * Dd;
    const float* Bptr = g_Wt + z * (Dd * Hh) + (size_t)h0 * Dd;

    MM_PROLOGUE(Aptr, Bptr)

    #pragma unroll
    for (int mt = 0; mt < 4; mt++) {
        const int row = r0 + wm + mt * 16 + g;
        #pragma unroll
        for (int nt = 0; nt < 4; nt++) {
            const int col = h0 + wn + nt * 8 + 2 * t;
            float2 bc = *reinterpret_cast<const float2*>(&bias[col]);
            float2 v0, v1;
            v0.x = c[mt][nt][0] + bc.x; v0.y = c[mt][nt][1] + bc.y;
            v1.x = c[mt][nt][2] + bc.x; v1.y = c[mt][nt][3] + bc.y;
            *reinterpret_cast<float2*>(&out[(size_t)row       * Hh + col]) = v0;
            *reinterpret_cast<float2*>(&out[(size_t)(row + 8) * Hh + col]) = v1;
        }
    }
}

// ---------------- kernel 3: P = exp(Q K^T * scale), Z row-sums (fused) ----------------
// grid: (N/128 k-tiles, N/128 q-tiles, B)  block: 256
__global__ __launch_bounds__(256, 2) void scores_fused_kernel() {
    __shared__ float rsum[128];

    const int b  = blockIdx.z;
    const int q0 = blockIdx.y * 128;
    const int k0 = blockIdx.x * 128;
    const float* Aptr = g_Q + (size_t)b * Nn * Hh + (size_t)q0 * Hh;
    const float* Bptr = g_K + (size_t)b * Nn * Hh + (size_t)k0 * Hh;

    MM_PROLOGUE(Aptr, Bptr)

    // ---- fused epilogue: exp, bf16 store, per-row Z partial sums ----
    __syncthreads();
    if (tid < 128) rsum[tid] = 0.0f;
    __syncthreads();

    const float scale = 0.0625f;    // 1/sqrt(256)
    __nv_bfloat16* Pb = g_P + (size_t)(b * Nn) * Nn;

    #pragma unroll
    for (int mt = 0; mt < 4; mt++) {
        const int row = wm + mt * 16 + g;
        float s0 = 0.0f, s1 = 0.0f;
        #pragma unroll
        for (int nt = 0; nt < 4; nt++) {
            const int col = k0 + wn + nt * 8 + 2 * t;
            float e0 = __expf(c[mt][nt][0] * scale);
            float e1 = __expf(c[mt][nt][1] * scale);
            float e2 = __expf(c[mt][nt][2] * scale);
            float e3 = __expf(c[mt][nt][3] * scale);
            s0 += e0 + e1;
            s1 += e2 + e3;
            *reinterpret_cast<__nv_bfloat162*>(&Pb[(size_t)(q0 + row)     * Nn + col]) =
                __floats2bfloat162_rn(e0, e1);
            *reinterpret_cast<__nv_bfloat162*>(&Pb[(size_t)(q0 + row + 8) * Nn + col]) =
                __floats2bfloat162_rn(e2, e3);
        }
        s0 += __shfl_xor_sync(0xFFFFFFFFu, s0, 1);
        s0 += __shfl_xor_sync(0xFFFFFFFFu, s0, 2);
        s1 += __shfl_xor_sync(0xFFFFFFFFu, s1, 1);
        s1 += __shfl_xor_sync(0xFFFFFFFFu, s1, 2);
        if (t == 0) {
            atomicAdd(&rsum[row],     s0);
            atomicAdd(&rsum[row + 8], s1);
        }
    }
    __syncthreads();
    if (tid < 128) atomicAdd(&g_z[b * Nn + q0 + tid], rsum[tid]);
}

// ---------------- kernel 4: invZ ----------------
__global__ void invz_kernel() {
    int i = blockIdx.x * 256 + threadIdx.x;
    g_c[i] = 1.0f / g_z[i];
}

// ---------------- kernel 5: w[b,k] = sum_q P[q,k] * invZ[q] ----------------
__global__ __launch_bounds__(128) void colsum_kernel() {
    const int b  = blockIdx.z;
    const int k2 = blockIdx.x * 128 + threadIdx.x;
    const int q0 = blockIdx.y * 256;

    __shared__ float iz[256];
    if (threadIdx.x < 128) {
        iz[threadIdx.x]       = g_c[b * Nn + q0 + threadIdx.x];
        iz[threadIdx.x + 128] = g_c[b * Nn + q0 + 128 + threadIdx.x];
    }
    __syncthreads();

    const __nv_bfloat162* Pb = reinterpret_cast<const __nv_bfloat162*>(g_P + (size_t)(b * Nn) * Nn);

    float ax = 0.0f, ay = 0.0f;
    #pragma unroll 4
    for (int q = 0; q < 256; q++) {
        float2 v = __bfloat1622float2(Pb[(size_t)(q0 + q) * (Nn / 2) + k2]);
        float w = iz[q];
        ax += v.x * w;
        ay += v.y * w;
    }
    atomicAdd(&g_w[b * Nn + 2 * k2],     ax);
    atomicAdd(&g_w[b * Nn + 2 * k2 + 1], ay);
}

// ---------------- kernel 6: out[b,h] = (1/N) sum_k w[b,k] V[b,k,h] ----------------
__global__ __launch_bounds__(256) void out_kernel(float* __restrict__ out) {
    const int b  = blockIdx.x;
    const int ks = blockIdx.y;
    const int h  = threadIdx.x;
    const float* Vb = g_V + (size_t)b * Nn * Hh;

    float acc = 0.0f;
    #pragma unroll 8
    for (int k = ks * 256; k < ks * 256 + 256; k++)
        acc += g_w[b * Nn + k] * Vb[(size_t)k * Hh + h];

    atomicAdd(&out[b * Hh + h], acc * (1.0f / Nn));
}

// ---------------- launch ----------------
extern "C" void kernel_launch(void* const* d_in, const int* in_sizes, int n_in,
                              void* d_out, int out_size) {
    const float* x  = (const float*)d_in[0];
    const float* Wq = (const float*)d_in[1];
    const float* bq = (const float*)d_in[2];
    const float* Wk = (const float*)d_in[3];
    const float* bk = (const float*)d_in[4];
    const float* Wv = (const float*)d_in[5];
    const float* bv = (const float*)d_in[6];
    float* out = (float*)d_out;

    cudaFuncSetAttribute(qkv_mma_kernel,
                         cudaFuncAttributeMaxDynamicSharedMemorySize, MM_DYN_SMEM);
    cudaFuncSetAttribute(scores_fused_kernel,
                         cudaFuncAttributeMaxDynamicSharedMemorySize, MM_DYN_SMEM);

    zero_kernel<<<128, 256>>>(out);
    transpose_w_kernel<<<dim3(8, 8, 3), dim3(32, 8)>>>(Wq, Wk, Wv);
    qkv_mma_kernel<<<dim3(Hh / 128, (Bb * Nn) / 128, 3), 256, MM_DYN_SMEM>>>(x, bq, bk, bv);
    scores_fused_kernel<<<dim3(Nn / 128, Nn / 128, Bb), 256, MM_DYN_SMEM>>>();
    invz_kernel<<<128, 256>>>();
    colsum_kernel<<<dim3(Nn / 256, Nn / 256, Bb), 128>>>();
    out_kernel<<<dim3(Bb, 16), 256>>>(out);
}

// round 9
// speedup vs baseline: 5.6950x; 1.4169x over previous
#include <cuda_runtime.h>
#include <cuda_bf16.h>
#include <math.h>
#include <stdint.h>

#define Bb 8
#define Nn 4096
#define Dd 256
#define Hh 256

// ---------------- static device scratch (allocation-free) ----------------
__device__ __nv_bfloat16 g_Qh[(size_t)Bb * Nn * Hh];     // 16.8 MB  Q in bf16
__device__ __nv_bfloat16 g_Kh[(size_t)Bb * Nn * Hh];     // 16.8 MB  K in bf16
__device__ float g_V[(size_t)Bb * Nn * Hh];              // 33.5 MB  V fp32
__device__ __nv_bfloat16 g_P[(size_t)Bb * Nn * Nn];      // 268 MB: P = exp(S)
__device__ float g_Wt[3 * Dd * Hh];                      // W^T for Q,K,V
__device__ float g_z[Bb * Nn];                           // row sums Z
__device__ float g_c[Bb * Nn];                           // 1/Z
__device__ float g_w[Bb * Nn];                           // column weights

// ================= helpers =================
__device__ __forceinline__ uint32_t smem_u32(const void* p) {
    uint32_t a;
    asm("{ .reg .u64 t; cvta.to.shared.u64 t, %1; cvt.u32.u64 %0, t; }" : "=r"(a) : "l"(p));
    return a;
}
__device__ __forceinline__ uint32_t lds32(uint32_t addr) {
    uint32_t v;
    asm volatile("ld.shared.b32 %0, [%1];" : "=r"(v) : "r"(addr));
    return v;
}
__device__ __forceinline__ void cpasync16(uint32_t dst, const void* src) {
    asm volatile("cp.async.ca.shared.global [%0], [%1], 16;" :: "r"(dst), "l"(src));
}
#define CP_COMMIT() asm volatile("cp.async.commit_group;" ::: "memory")
#define CP_WAIT(N)  asm volatile("cp.async.wait_group %0;" :: "n"(N) : "memory")

__device__ __forceinline__ void mma_tf32(float* c,
                                         uint32_t a0, uint32_t a1, uint32_t a2, uint32_t a3,
                                         uint32_t b0, uint32_t b1) {
    asm volatile(
        "mma.sync.aligned.m16n8k8.row.col.f32.tf32.tf32.f32 "
        "{%0,%1,%2,%3}, {%4,%5,%6,%7}, {%8,%9}, {%0,%1,%2,%3};"
        : "+f"(c[0]), "+f"(c[1]), "+f"(c[2]), "+f"(c[3])
        : "r"(a0), "r"(a1), "r"(a2), "r"(a3), "r"(b0), "r"(b1));
}
__device__ __forceinline__ void mma_bf16(float* c,
                                         uint32_t a0, uint32_t a1, uint32_t a2, uint32_t a3,
                                         uint32_t b0, uint32_t b1) {
    asm volatile(
        "mma.sync.aligned.m16n8k16.row.col.f32.bf16.bf16.f32 "
        "{%0,%1,%2,%3}, {%4,%5,%6,%7}, {%8,%9}, {%0,%1,%2,%3};"
        : "+f"(c[0]), "+f"(c[1]), "+f"(c[2]), "+f"(c[3])
        : "r"(a0), "r"(a1), "r"(a2), "r"(a3), "r"(b0), "r"(b1));
}
#define SW128(o) ((o) ^ (((o) >> 3) & 0x70u))

#define MM_DYN_SMEM 65536   // 2 buffers x (A 16KB + B 16KB)

// ---------------- kernel 0: zero accumulators ----------------
__global__ void zero_kernel(float* __restrict__ out) {
    int i = blockIdx.x * 256 + threadIdx.x;
    if (i < Bb * Nn) { g_w[i] = 0.0f; g_z[i] = 0.0f; }
    if (i < Bb * Hh) out[i] = 0.0f;
}

// ---------------- kernel 1: W transpose (768 KB, trivial) ----------------
__global__ void transpose_w_kernel(const float* __restrict__ Wq,
                                   const float* __restrict__ Wk,
                                   const float* __restrict__ Wv) {
    const float* W = (blockIdx.z == 0) ? Wq : (blockIdx.z == 1) ? Wk : Wv;
    float* Wt = g_Wt + blockIdx.z * (Dd * Hh);
    __shared__ float t[32][33];
    const int x0 = blockIdx.x * 32, y0 = blockIdx.y * 32;
    #pragma unroll
    for (int i = threadIdx.y; i < 32; i += 8)
        t[i][threadIdx.x] = W[(size_t)(y0 + i) * Hh + x0 + threadIdx.x];
    __syncthreads();
    #pragma unroll
    for (int i = threadIdx.y; i < 32; i += 8)
        Wt[(size_t)(x0 + i) * Dd + y0 + threadIdx.x] = t[threadIdx.x][i];
}

// ===== fp32/tf32 MMA mainloop (for QKV projection; inputs fp32) =====
struct MmaCtx {
    uint32_t aBase, bBase, swz;
    uint32_t stsOff[4];
    const float* Aq;
    const float* Bk;
};

__device__ __forceinline__ void mm_issue(const MmaCtx& cx, uint32_t sb, int ch, int buf) {
    const uint32_t bq = sb + (uint32_t)buf * 32768u;
    const uint32_t bk = bq + 16384u;
    const float* qa = cx.Aq + ch * 32;
    const float* ka = cx.Bk + ch * 32;
    #pragma unroll
    for (int i = 0; i < 4; i++) {
        cpasync16(bq + cx.stsOff[i], qa + (size_t)i * 32 * 256);
        cpasync16(bk + cx.stsOff[i], ka + (size_t)i * 32 * 256);
    }
    CP_COMMIT();
}

__device__ __forceinline__ void mm_compute(const MmaCtx& cx, int buf,
                                           float c[4][4][4], int t) {
    const uint32_t off = (uint32_t)buf * 32768u;
    const uint32_t aB = cx.aBase + off;
    const uint32_t bB = cx.bBase + off + 16384u;
    #pragma unroll
    for (int ks = 0; ks < 4; ks++) {
        const uint32_t ct0 = (uint32_t)(ks * 32 + t * 4)      ^ cx.swz;
        const uint32_t ct1 = (uint32_t)(ks * 32 + t * 4 + 16) ^ cx.swz;
        uint32_t b0[4], b1[4];
        #pragma unroll
        for (int nt = 0; nt < 4; nt++) {
            b0[nt] = lds32(bB + nt * 1024 + ct0);
            b1[nt] = lds32(bB + nt * 1024 + ct1);
        }
        #pragma unroll
        for (int mt = 0; mt < 4; mt++) {
            uint32_t a0 = lds32(aB + mt * 2048 +        ct0);
            uint32_t a1 = lds32(aB + mt * 2048 + 1024 + ct0);
            uint32_t a2 = lds32(aB + mt * 2048 +        ct1);
            uint32_t a3 = lds32(aB + mt * 2048 + 1024 + ct1);
            #pragma unroll
            for (int nt = 0; nt < 4; nt++)
                mma_tf32(c[mt][nt], a0, a1, a2, a3, b0[nt], b1[nt]);
        }
    }
}

#define MM_COMMON_IDX                                                            \
    extern __shared__ float dynsm[];                                             \
    const uint32_t sb = smem_u32(dynsm);                                         \
    const int tid  = threadIdx.x;                                                \
    const int wid  = tid >> 5;                                                   \
    const int lane = tid & 31;                                                   \
    const int g = lane >> 2, t = lane & 3;                                       \
    const int wm = (wid & 1) * 64;                                               \
    const int wn = (wid >> 1) * 32;                                              \
    const int lr = tid >> 3;                                                     \
    const int lc = tid & 7;                                                      \
    float c[4][4][4];                                                            \
    _Pragma("unroll")                                                            \
    for (int mt = 0; mt < 4; mt++)                                               \
        _Pragma("unroll")                                                        \
        for (int nt = 0; nt < 4; nt++)                                           \
            _Pragma("unroll")                                                    \
            for (int r = 0; r < 4; r++)                                          \
                c[mt][nt][r] = 0.0f;

// ---------------- kernel 2: QKV projection via mma.sync tf32 ----------------
// grid: (Hh/128, (B*N)/128, 3)  block: 256.  Q,K written bf16; V fp32.
__global__ __launch_bounds__(256, 2) void qkv_mma_kernel(
    const float* __restrict__ x,
    const float* __restrict__ bq, const float* __restrict__ bk, const float* __restrict__ bv)
{
    const int z  = blockIdx.z;
    const float* bias = (z == 0) ? bq : (z == 1) ? bk : bv;
    const int r0 = blockIdx.y * 128;
    const int h0 = blockIdx.x * 128;

    MM_COMMON_IDX

    MmaCtx cx;
    #pragma unroll
    for (int i = 0; i < 4; i++)
        cx.stsOff[i] = SW128((uint32_t)((lr + 32 * i) * 128 + lc * 16));
    cx.aBase = sb + (uint32_t)(wm + g) * 128;
    cx.bBase = sb + (uint32_t)(wn + g) * 128;
    cx.swz   = (uint32_t)g << 4;
    cx.Aq = x + (size_t)r0 * Dd + (size_t)lr * 256 + lc * 4;
    cx.Bk = g_Wt + z * (Dd * Hh) + (size_t)h0 * Dd + (size_t)lr * 256 + lc * 4;

    mm_issue(cx, sb, 0, 0);
    mm_issue(cx, sb, 1, 1);
    #pragma unroll 1
    for (int ch = 0; ch < 8; ch++) {
        if (ch == 7) { CP_WAIT(0); } else { CP_WAIT(1); }
        __syncthreads();
        mm_compute(cx, ch & 1, c, t);
        __syncthreads();
        if (ch + 2 < 8) mm_issue(cx, sb, ch + 2, ch & 1);
    }

    if (z == 2) {
        #pragma unroll
        for (int mt = 0; mt < 4; mt++) {
            const int row = r0 + wm + mt * 16 + g;
            #pragma unroll
            for (int nt = 0; nt < 4; nt++) {
                const int col = h0 + wn + nt * 8 + 2 * t;
                float2 bc = *reinterpret_cast<const float2*>(&bias[col]);
                float2 v0, v1;
                v0.x = c[mt][nt][0] + bc.x; v0.y = c[mt][nt][1] + bc.y;
                v1.x = c[mt][nt][2] + bc.x; v1.y = c[mt][nt][3] + bc.y;
                *reinterpret_cast<float2*>(&g_V[(size_t)row       * Hh + col]) = v0;
                *reinterpret_cast<float2*>(&g_V[(size_t)(row + 8) * Hh + col]) = v1;
            }
        }
    } else {
        __nv_bfloat16* outh = (z == 0) ? g_Qh : g_Kh;
        #pragma unroll
        for (int mt = 0; mt < 4; mt++) {
            const int row = r0 + wm + mt * 16 + g;
            #pragma unroll
            for (int nt = 0; nt < 4; nt++) {
                const int col = h0 + wn + nt * 8 + 2 * t;
                float2 bc = *reinterpret_cast<const float2*>(&bias[col]);
                *reinterpret_cast<__nv_bfloat162*>(&outh[(size_t)row       * Hh + col]) =
                    __floats2bfloat162_rn(c[mt][nt][0] + bc.x, c[mt][nt][1] + bc.y);
                *reinterpret_cast<__nv_bfloat162*>(&outh[(size_t)(row + 8) * Hh + col]) =
                    __floats2bfloat162_rn(c[mt][nt][2] + bc.x, c[mt][nt][3] + bc.y);
            }
        }
    }
}

// ===== bf16 MMA mainloop pieces (scores) =====
// SMEM tile per buffer: 128 rows x 64 bf16 (128 B/row) per matrix.
// Chunk covers k=64 (4 x k16 MMA steps); 4 chunks for K=256.
struct MmaCtxH {
    uint32_t aBase, bBase, swz;
    uint32_t stsOff[4];
    const __nv_bfloat16* Aq;
    const __nv_bfloat16* Bk;
};

__device__ __forceinline__ void mm_issue_h(const MmaCtxH& cx, uint32_t sb, int ch, int buf) {
    const uint32_t bq = sb + (uint32_t)buf * 32768u;
    const uint32_t bk = bq + 16384u;
    const __nv_bfloat16* qa = cx.Aq + ch * 64;
    const __nv_bfloat16* ka = cx.Bk + ch * 64;
    #pragma unroll
    for (int i = 0; i < 4; i++) {
        cpasync16(bq + cx.stsOff[i], qa + (size_t)i * 32 * 256);
        cpasync16(bk + cx.stsOff[i], ka + (size_t)i * 32 * 256);
    }
    CP_COMMIT();
}

__device__ __forceinline__ void mm_compute_h(const MmaCtxH& cx, int buf,
                                             float c[4][4][4], int t) {
    const uint32_t off = (uint32_t)buf * 32768u;
    const uint32_t aB = cx.aBase + off;
    const uint32_t bB = cx.bBase + off + 16384u;
    #pragma unroll
    for (int ks = 0; ks < 4; ks++) {
        // byte offsets identical to the tf32 layout: a0/b0 @ 4t, a2/b1 @ 4t+16
        const uint32_t ct0 = (uint32_t)(ks * 32 + t * 4)      ^ cx.swz;
        const uint32_t ct1 = (uint32_t)(ks * 32 + t * 4 + 16) ^ cx.swz;
        uint32_t b0[4], b1[4];
        #pragma unroll
        for (int nt = 0; nt < 4; nt++) {
            b0[nt] = lds32(bB + nt * 1024 + ct0);
            b1[nt] = lds32(bB + nt * 1024 + ct1);
        }
        #pragma unroll
        for (int mt = 0; mt < 4; mt++) {
            uint32_t a0 = lds32(aB + mt * 2048 +        ct0);
            uint32_t a1 = lds32(aB + mt * 2048 + 1024 + ct0);
            uint32_t a2 = lds32(aB + mt * 2048 +        ct1);
            uint32_t a3 = lds32(aB + mt * 2048 + 1024 + ct1);
            #pragma unroll
            for (int nt = 0; nt < 4; nt++)
                mma_bf16(c[mt][nt], a0, a1, a2, a3, b0[nt], b1[nt]);
        }
    }
}

// ---------------- kernel 3: P = exp(Q K^T * scale), Z row-sums (bf16 MMA) ----------------
// grid: (N/128 k-tiles, N/128 q-tiles, B)  block: 256
__global__ __launch_bounds__(256, 2) void scores_fused_kernel() {
    __shared__ float rsum[128];

    const int b  = blockIdx.z;
    const int q0 = blockIdx.y * 128;
    const int k0 = blockIdx.x * 128;

    MM_COMMON_IDX

    MmaCtxH cx;
    #pragma unroll
    for (int i = 0; i < 4; i++)
        cx.stsOff[i] = SW128((uint32_t)((lr + 32 * i) * 128 + lc * 16));
    cx.aBase = sb + (uint32_t)(wm + g) * 128;
    cx.bBase = sb + (uint32_t)(wn + g) * 128;
    cx.swz   = (uint32_t)g << 4;
    cx.Aq = g_Qh + (size_t)(b * Nn + q0) * Hh + (size_t)lr * 256 + lc * 8;
    cx.Bk = g_Kh + (size_t)(b * Nn + k0) * Hh + (size_t)lr * 256 + lc * 8;

    mm_issue_h(cx, sb, 0, 0);
    mm_issue_h(cx, sb, 1, 1);
    #pragma unroll 1
    for (int ch = 0; ch < 4; ch++) {
        if (ch == 3) { CP_WAIT(0); } else { CP_WAIT(1); }
        __syncthreads();
        mm_compute_h(cx, ch & 1, c, t);
        __syncthreads();
        if (ch + 2 < 4) mm_issue_h(cx, sb, ch + 2, ch & 1);
    }

    // ---- fused epilogue: exp, bf16 store, per-row Z partial sums ----
    if (tid < 128) rsum[tid] = 0.0f;
    __syncthreads();

    const float scale = 0.0625f;    // 1/sqrt(256)
    __nv_bfloat16* Pb = g_P + (size_t)(b * Nn) * Nn;

    #pragma unroll
    for (int mt = 0; mt < 4; mt++) {
        const int row = wm + mt * 16 + g;
        float s0 = 0.0f, s1 = 0.0f;
        #pragma unroll
        for (int nt = 0; nt < 4; nt++) {
            const int col = k0 + wn + nt * 8 + 2 * t;
            float e0 = __expf(c[mt][nt][0] * scale);
            float e1 = __expf(c[mt][nt][1] * scale);
            float e2 = __expf(c[mt][nt][2] * scale);
            float e3 = __expf(c[mt][nt][3] * scale);
            s0 += e0 + e1;
            s1 += e2 + e3;
            *reinterpret_cast<__nv_bfloat162*>(&Pb[(size_t)(q0 + row)     * Nn + col]) =
                __floats2bfloat162_rn(e0, e1);
            *reinterpret_cast<__nv_bfloat162*>(&Pb[(size_t)(q0 + row + 8) * Nn + col]) =
                __floats2bfloat162_rn(e2, e3);
        }
        s0 += __shfl_xor_sync(0xFFFFFFFFu, s0, 1);
        s0 += __shfl_xor_sync(0xFFFFFFFFu, s0, 2);
        s1 += __shfl_xor_sync(0xFFFFFFFFu, s1, 1);
        s1 += __shfl_xor_sync(0xFFFFFFFFu, s1, 2);
        if (t == 0) {
            atomicAdd(&rsum[row],     s0);
            atomicAdd(&rsum[row + 8], s1);
        }
    }
    __syncthreads();
    if (tid < 128) atomicAdd(&g_z[b * Nn + q0 + tid], rsum[tid]);
}

// ---------------- kernel 4: invZ ----------------
__global__ void invz_kernel() {
    int i = blockIdx.x * 256 + threadIdx.x;
    g_c[i] = 1.0f / g_z[i];
}

// ---------------- kernel 5: w[b,k] = sum_q P[q,k] * invZ[q] ----------------
__global__ __launch_bounds__(128) void colsum_kernel() {
    const int b  = blockIdx.z;
    const int k2 = blockIdx.x * 128 + threadIdx.x;
    const int q0 = blockIdx.y * 256;

    __shared__ float iz[256];
    if (threadIdx.x < 128) {
        iz[threadIdx.x]       = g_c[b * Nn + q0 + threadIdx.x];
        iz[threadIdx.x + 128] = g_c[b * Nn + q0 + 128 + threadIdx.x];
    }
    __syncthreads();

    const __nv_bfloat162* Pb = reinterpret_cast<const __nv_bfloat162*>(g_P + (size_t)(b * Nn) * Nn);

    float ax = 0.0f, ay = 0.0f;
    #pragma unroll 4
    for (int q = 0; q < 256; q++) {
        float2 v = __bfloat1622float2(Pb[(size_t)(q0 + q) * (Nn / 2) + k2]);
        float w = iz[q];
        ax += v.x * w;
        ay += v.y * w;
    }
    atomicAdd(&g_w[b * Nn + 2 * k2],     ax);
    atomicAdd(&g_w[b * Nn + 2 * k2 + 1], ay);
}

// ---------------- kernel 6: out[b,h] = (1/N) sum_k w[b,k] V[b,k,h] ----------------
__global__ __launch_bounds__(256) void out_kernel(float* __restrict__ out) {
    const int b  = blockIdx.x;
    const int ks = blockIdx.y;
    const int h  = threadIdx.x;
    const float* Vb = g_V + (size_t)b * Nn * Hh;

    float acc = 0.0f;
    #pragma unroll 8
    for (int k = ks * 256; k < ks * 256 + 256; k++)
        acc += g_w[b * Nn + k] * Vb[(size_t)k * Hh + h];

    atomicAdd(&out[b * Hh + h], acc * (1.0f / Nn));
}

// ---------------- launch ----------------
extern "C" void kernel_launch(void* const* d_in, const int* in_sizes, int n_in,
                              void* d_out, int out_size) {
    const float* x  = (const float*)d_in[0];
    const float* Wq = (const float*)d_in[1];
    const float* bq = (const float*)d_in[2];
    const float* Wk = (const float*)d_in[3];
    const float* bk = (const float*)d_in[4];
    const float* Wv = (const float*)d_in[5];
    const float* bv = (const float*)d_in[6];
    float* out = (float*)d_out;

    cudaFuncSetAttribute(qkv_mma_kernel,
                         cudaFuncAttributeMaxDynamicSharedMemorySize, MM_DYN_SMEM);
    cudaFuncSetAttribute(scores_fused_kernel,
                         cudaFuncAttributeMaxDynamicSharedMemorySize, MM_DYN_SMEM);

    zero_kernel<<<128, 256>>>(out);
    transpose_w_kernel<<<dim3(8, 8, 3), dim3(32, 8)>>>(Wq, Wk, Wv);
    qkv_mma_kernel<<<dim3(Hh / 128, (Bb * Nn) / 128, 3), 256, MM_DYN_SMEM>>>(x, bq, bk, bv);
    scores_fused_kernel<<<dim3(Nn / 128, Nn / 128, Bb), 256, MM_DYN_SMEM>>>();
    invz_kernel<<<128, 256>>>();
    colsum_kernel<<<dim3(Nn / 256, Nn / 256, Bb), 128>>>();
    out_kernel<<<dim3(Bb, 16), 256>>>(out);
}

// round 11
// speedup vs baseline: 6.3493x; 1.1149x over previous
#include <cuda_runtime.h>
#include <cuda_fp16.h>
#include <math.h>
#include <stdint.h>

#define Bb 8
#define Nn 4096
#define Dd 256
#define Hh 256

// ---------------- static device scratch (allocation-free) ----------------
__device__ __half g_xh[(size_t)Bb * Nn * Dd];            // 16.8 MB  x in fp16
__device__ __half g_Qh[(size_t)Bb * Nn * Hh];            // 16.8 MB  Q in fp16
__device__ __half g_Kh[(size_t)Bb * Nn * Hh];            // 16.8 MB  K in fp16
__device__ float  g_V[(size_t)Bb * Nn * Hh];             // 33.5 MB  V fp32
__device__ __half g_P[(size_t)Bb * Nn * Nn];             // 268 MB: P = exp(S) fp16
__device__ __half g_Wth[3 * Dd * Hh];                    // W^T fp16 for Q,K,V
__device__ float  g_z[Bb * Nn];                          // row sums Z
__device__ float  g_c[Bb * Nn];                          // 1/Z
__device__ float  g_w[Bb * Nn];                          // column weights

// ================= helpers =================
__device__ __forceinline__ uint32_t smem_u32(const void* p) {
    uint32_t a;
    asm("{ .reg .u64 t; cvta.to.shared.u64 t, %1; cvt.u32.u64 %0, t; }" : "=r"(a) : "l"(p));
    return a;
}
__device__ __forceinline__ uint32_t lds32(uint32_t addr) {
    uint32_t v;
    asm volatile("ld.shared.b32 %0, [%1];" : "=r"(v) : "r"(addr));
    return v;
}
__device__ __forceinline__ void cpasync16(uint32_t dst, const void* src) {
    asm volatile("cp.async.ca.shared.global [%0], [%1], 16;" :: "r"(dst), "l"(src));
}
#define CP_COMMIT() asm volatile("cp.async.commit_group;" ::: "memory")
#define CP_WAIT(N)  asm volatile("cp.async.wait_group %0;" :: "n"(N) : "memory")

// fp16 inputs, fp32 accumulate (QKV projection)
__device__ __forceinline__ void mma_f16f32(float* c,
                                           uint32_t a0, uint32_t a1, uint32_t a2, uint32_t a3,
                                           uint32_t b0, uint32_t b1) {
    asm volatile(
        "mma.sync.aligned.m16n8k16.row.col.f32.f16.f16.f32 "
        "{%0,%1,%2,%3}, {%4,%5,%6,%7}, {%8,%9}, {%0,%1,%2,%3};"
        : "+f"(c[0]), "+f"(c[1]), "+f"(c[2]), "+f"(c[3])
        : "r"(a0), "r"(a1), "r"(a2), "r"(a3), "r"(b0), "r"(b1));
}
// fp16 inputs, fp16 accumulate (scores) — 2 packed f16x2 accumulator regs
__device__ __forceinline__ void mma_f16(uint32_t* c,
                                        uint32_t a0, uint32_t a1, uint32_t a2, uint32_t a3,
                                        uint32_t b0, uint32_t b1) {
    asm volatile(
        "mma.sync.aligned.m16n8k16.row.col.f16.f16.f16.f16 "
        "{%0,%1}, {%2,%3,%4,%5}, {%6,%7}, {%0,%1};"
        : "+r"(c[0]), "+r"(c[1])
        : "r"(a0), "r"(a1), "r"(a2), "r"(a3), "r"(b0), "r"(b1));
}
#define SW128(o) ((o) ^ (((o) >> 3) & 0x70u))

#define QKV_DYN_SMEM 65536    // 2 buffers x (A 16KB + B 16KB)
#define SC_DYN_SMEM  98304    // 2 buffers x (A 16KB + B 32KB)

// ---------------- kernel 0: zero accumulators ----------------
__global__ void zero_kernel(float* __restrict__ out) {
    int i = blockIdx.x * 256 + threadIdx.x;
    if (i < Bb * Nn) { g_w[i] = 0.0f; g_z[i] = 0.0f; }
    if (i < Bb * Hh) out[i] = 0.0f;
}

// ---------------- kernel 0b: x -> fp16 ----------------
__global__ __launch_bounds__(256) void convert_x_kernel(const float* __restrict__ x) {
    int i = blockIdx.x * 256 + threadIdx.x;           // one float2 -> half2
    float2 v = reinterpret_cast<const float2*>(x)[i];
    reinterpret_cast<__half2*>(g_xh)[i] = __floats2half2_rn(v.x, v.y);
}

// ---------------- kernel 1: W transpose -> fp16 ----------------
__global__ void transpose_w_kernel(const float* __restrict__ Wq,
                                   const float* __restrict__ Wk,
                                   const float* __restrict__ Wv) {
    const float* W = (blockIdx.z == 0) ? Wq : (blockIdx.z == 1) ? Wk : Wv;
    __half* Wt = g_Wth + blockIdx.z * (Dd * Hh);
    __shared__ float t[32][33];
    const int x0 = blockIdx.x * 32, y0 = blockIdx.y * 32;
    #pragma unroll
    for (int i = threadIdx.y; i < 32; i += 8)
        t[i][threadIdx.x] = W[(size_t)(y0 + i) * Hh + x0 + threadIdx.x];
    __syncthreads();
    #pragma unroll
    for (int i = threadIdx.y; i < 32; i += 8)
        Wt[(size_t)(x0 + i) * Dd + y0 + threadIdx.x] = __float2half(t[threadIdx.x][i]);
}

// ---------------- kernel 2: QKV projection, fp16 inputs / f32 acc ----------------
// CTA tile 128(r) x 128(h), K=256 in 4 chunks of k64. Warp tile 64x32.
// grid: (Hh/128, (B*N)/128, 3)  block: 256
__global__ __launch_bounds__(256, 2) void qkv_mma_kernel(
    const float* __restrict__ bq, const float* __restrict__ bk, const float* __restrict__ bv)
{
    extern __shared__ float dynsm[];
    const uint32_t sb = smem_u32(dynsm);
    const int tid  = threadIdx.x;
    const int wid  = tid >> 5;
    const int lane = tid & 31;
    const int g = lane >> 2, t = lane & 3;
    const int wm = (wid & 1) * 64;
    const int wn = (wid >> 1) * 32;
    const int lr = tid >> 3;
    const int lc = tid & 7;

    const int z  = blockIdx.z;
    const float* bias = (z == 0) ? bq : (z == 1) ? bk : bv;
    const int r0 = blockIdx.y * 128;
    const int h0 = blockIdx.x * 128;

    const uint32_t stsOff = SW128((uint32_t)(lr * 128 + lc * 16));
    const __half* Aq = g_xh + (size_t)r0 * Dd + (size_t)lr * 256 + lc * 8;
    const __half* Bk = g_Wth + z * (Dd * Hh) + (size_t)h0 * Dd + (size_t)lr * 256 + lc * 8;
    const uint32_t aBase = sb + (uint32_t)(wm + g) * 128;
    const uint32_t bBase = sb + 16384u + (uint32_t)(wn + g) * 128;
    const uint32_t swz = (uint32_t)g << 4;

    float c[4][4][4];
    #pragma unroll
    for (int mt = 0; mt < 4; mt++)
        #pragma unroll
        for (int nt = 0; nt < 4; nt++)
            #pragma unroll
            for (int r = 0; r < 4; r++) c[mt][nt][r] = 0.0f;

    auto issue = [&](int ch, int buf) {
        const uint32_t ba = sb + (uint32_t)buf * 32768u;
        const __half* qa = Aq + ch * 64;
        const __half* ka = Bk + ch * 64;
        #pragma unroll
        for (int i = 0; i < 4; i++) {
            cpasync16(ba + stsOff + i * 4096u,          qa + (size_t)i * 32 * 256);
            cpasync16(ba + 16384u + stsOff + i * 4096u, ka + (size_t)i * 32 * 256);
        }
        CP_COMMIT();
    };
    auto compute = [&](int buf) {
        const uint32_t aB = aBase + (uint32_t)buf * 32768u;
        const uint32_t bB = bBase + (uint32_t)buf * 32768u;
        #pragma unroll
        for (int ks = 0; ks < 4; ks++) {
            const uint32_t ct0 = (uint32_t)(ks * 32 + t * 4)      ^ swz;
            const uint32_t ct1 = (uint32_t)(ks * 32 + t * 4 + 16) ^ swz;
            uint32_t b0[4], b1[4];
            #pragma unroll
            for (int nt = 0; nt < 4; nt++) {
                b0[nt] = lds32(bB + nt * 1024 + ct0);
                b1[nt] = lds32(bB + nt * 1024 + ct1);
            }
            #pragma unroll
            for (int mt = 0; mt < 4; mt++) {
                uint32_t a0 = lds32(aB + mt * 2048 +        ct0);
                uint32_t a1 = lds32(aB + mt * 2048 + 1024 + ct0);
                uint32_t a2 = lds32(aB + mt * 2048 +        ct1);
                uint32_t a3 = lds32(aB + mt * 2048 + 1024 + ct1);
                #pragma unroll
                for (int nt = 0; nt < 4; nt++)
                    mma_f16f32(c[mt][nt], a0, a1, a2, a3, b0[nt], b1[nt]);
            }
        }
    };

    issue(0, 0); issue(1, 1);
    #pragma unroll 1
    for (int ch = 0; ch < 4; ch++) {
        if (ch == 3) { CP_WAIT(0); } else { CP_WAIT(1); }
        __syncthreads();
        compute(ch & 1);
        __syncthreads();
        if (ch + 2 < 4) issue(ch + 2, ch & 1);
    }

    if (z == 2) {
        #pragma unroll
        for (int mt = 0; mt < 4; mt++) {
            const int row = r0 + wm + mt * 16 + g;
            #pragma unroll
            for (int nt = 0; nt < 4; nt++) {
                const int col = h0 + wn + nt * 8 + 2 * t;
                float2 bc = *reinterpret_cast<const float2*>(&bias[col]);
                float2 v0, v1;
                v0.x = c[mt][nt][0] + bc.x; v0.y = c[mt][nt][1] + bc.y;
                v1.x = c[mt][nt][2] + bc.x; v1.y = c[mt][nt][3] + bc.y;
                *reinterpret_cast<float2*>(&g_V[(size_t)row       * Hh + col]) = v0;
                *reinterpret_cast<float2*>(&g_V[(size_t)(row + 8) * Hh + col]) = v1;
            }
        }
    } else {
        __half* outh = (z == 0) ? g_Qh : g_Kh;
        #pragma unroll
        for (int mt = 0; mt < 4; mt++) {
            const int row = r0 + wm + mt * 16 + g;
            #pragma unroll
            for (int nt = 0; nt < 4; nt++) {
                const int col = h0 + wn + nt * 8 + 2 * t;
                float2 bc = *reinterpret_cast<const float2*>(&bias[col]);
                *reinterpret_cast<__half2*>(&outh[(size_t)row       * Hh + col]) =
                    __floats2half2_rn(c[mt][nt][0] + bc.x, c[mt][nt][1] + bc.y);
                *reinterpret_cast<__half2*>(&outh[(size_t)(row + 8) * Hh + col]) =
                    __floats2half2_rn(c[mt][nt][2] + bc.x, c[mt][nt][3] + bc.y);
            }
        }
    }
}

// ---------------- kernel 3: P = exp(Q K^T * scale), Z row-sums ----------------
// fp16 inputs, fp16 accumulators. CTA tile 128(q) x 256(k); warp tile 64x64.
// K=256 in 4 chunks of k64. grid: (N/256, N/128, B)  block: 256
__global__ __launch_bounds__(256, 2) void scores_fused_kernel() {
    extern __shared__ float dynsm[];
    __shared__ float rsum[128];
    const uint32_t sb = smem_u32(dynsm);
    const int tid  = threadIdx.x;
    const int wid  = tid >> 5;
    const int lane = tid & 31;
    const int g = lane >> 2, t = lane & 3;
    const int wm = (wid & 1) * 64;
    const int wn = (wid >> 1) * 64;            // 4 n-warps x 64
    const int lr = tid >> 3;
    const int lc = tid & 7;

    const int b  = blockIdx.z;
    const int q0 = blockIdx.y * 128;
    const int k0 = blockIdx.x * 256;

    const uint32_t stsOff = SW128((uint32_t)(lr * 128 + lc * 16));
    const __half* Aq = g_Qh + (size_t)(b * Nn + q0) * Hh + (size_t)lr * 256 + lc * 8;
    const __half* Bk = g_Kh + (size_t)(b * Nn + k0) * Hh + (size_t)lr * 256 + lc * 8;
    const uint32_t aBase = sb + (uint32_t)(wm + g) * 128;
    const uint32_t bBase = sb + 16384u + (uint32_t)(wn + g) * 128;
    const uint32_t swz = (uint32_t)g << 4;

    uint32_t c[4][8][2];   // f16x2 accumulators: 64 regs
    #pragma unroll
    for (int mt = 0; mt < 4; mt++)
        #pragma unroll
        for (int nt = 0; nt < 8; nt++) { c[mt][nt][0] = 0u; c[mt][nt][1] = 0u; }

    auto issue = [&](int ch, int buf) {
        const uint32_t ba = sb + (uint32_t)buf * 49152u;
        const __half* qa = Aq + ch * 64;
        const __half* ka = Bk + ch * 64;
        #pragma unroll
        for (int i = 0; i < 4; i++)
            cpasync16(ba + stsOff + i * 4096u, qa + (size_t)i * 32 * 256);
        #pragma unroll
        for (int i = 0; i < 8; i++)
            cpasync16(ba + 16384u + stsOff + i * 4096u, ka + (size_t)i * 32 * 256);
        CP_COMMIT();
    };
    auto compute = [&](int buf) {
        const uint32_t aB = aBase + (uint32_t)buf * 49152u;
        const uint32_t bB = bBase + (uint32_t)buf * 49152u;
        #pragma unroll
        for (int ks = 0; ks < 4; ks++) {
            const uint32_t ct0 = (uint32_t)(ks * 32 + t * 4)      ^ swz;
            const uint32_t ct1 = (uint32_t)(ks * 32 + t * 4 + 16) ^ swz;
            uint32_t b0[8], b1[8];
            #pragma unroll
            for (int nt = 0; nt < 8; nt++) {
                b0[nt] = lds32(bB + nt * 1024 + ct0);
                b1[nt] = lds32(bB + nt * 1024 + ct1);
            }
            #pragma unroll
            for (int mt = 0; mt < 4; mt++) {
                uint32_t a0 = lds32(aB + mt * 2048 +        ct0);
                uint32_t a1 = lds32(aB + mt * 2048 + 1024 + ct0);
                uint32_t a2 = lds32(aB + mt * 2048 +        ct1);
                uint32_t a3 = lds32(aB + mt * 2048 + 1024 + ct1);
                #pragma unroll
                for (int nt = 0; nt < 8; nt++)
                    mma_f16(c[mt][nt], a0, a1, a2, a3, b0[nt], b1[nt]);
            }
        }
    };

    issue(0, 0); issue(1, 1);
    #pragma unroll 1
    for (int ch = 0; ch < 4; ch++) {
        if (ch == 3) { CP_WAIT(0); } else { CP_WAIT(1); }
        __syncthreads();
        compute(ch & 1);
        __syncthreads();
        if (ch + 2 < 4) issue(ch + 2, ch & 1);
    }

    // ---- fused epilogue: exp, fp16 store, per-row Z partial sums ----
    if (tid < 128) rsum[tid] = 0.0f;
    __syncthreads();

    const float scale = 0.0625f;    // 1/sqrt(256)
    __half* Ph = g_P + (size_t)(b * Nn) * Nn;

    #pragma unroll
    for (int mt = 0; mt < 4; mt++) {
        const int row = wm + mt * 16 + g;
        float s0 = 0.0f, s1 = 0.0f;
        #pragma unroll
        for (int nt = 0; nt < 8; nt++) {
            const int col = k0 + wn + nt * 8 + 2 * t;
            float2 v0 = __half22float2(*reinterpret_cast<__half2*>(&c[mt][nt][0]));
            float2 v1 = __half22float2(*reinterpret_cast<__half2*>(&c[mt][nt][1]));
            float e0 = __expf(v0.x * scale);
            float e1 = __expf(v0.y * scale);
            float e2 = __expf(v1.x * scale);
            float e3 = __expf(v1.y * scale);
            s0 += e0 + e1;
            s1 += e2 + e3;
            *reinterpret_cast<__half2*>(&Ph[(size_t)(q0 + row)     * Nn + col]) =
                __floats2half2_rn(e0, e1);
            *reinterpret_cast<__half2*>(&Ph[(size_t)(q0 + row + 8) * Nn + col]) =
                __floats2half2_rn(e2, e3);
        }
        s0 += __shfl_xor_sync(0xFFFFFFFFu, s0, 1);
        s0 += __shfl_xor_sync(0xFFFFFFFFu, s0, 2);
        s1 += __shfl_xor_sync(0xFFFFFFFFu, s1, 1);
        s1 += __shfl_xor_sync(0xFFFFFFFFu, s1, 2);
        if (t == 0) {
            atomicAdd(&rsum[row],     s0);
            atomicAdd(&rsum[row + 8], s1);
        }
    }
    __syncthreads();
    if (tid < 128) atomicAdd(&g_z[b * Nn + q0 + tid], rsum[tid]);
}

// ---------------- kernel 4: invZ ----------------
__global__ void invz_kernel() {
    int i = blockIdx.x * 256 + threadIdx.x;
    g_c[i] = 1.0f / g_z[i];
}

// ---------------- kernel 5: w[b,k] = sum_q P[q,k] * invZ[q] ----------------
__global__ __launch_bounds__(128) void colsum_kernel() {
    const int b  = blockIdx.z;
    const int k2 = blockIdx.x * 128 + threadIdx.x;
    const int q0 = blockIdx.y * 256;

    __shared__ float iz[256];
    if (threadIdx.x < 128) {
        iz[threadIdx.x]       = g_c[b * Nn + q0 + threadIdx.x];
        iz[threadIdx.x + 128] = g_c[b * Nn + q0 + 128 + threadIdx.x];
    }
    __syncthreads();

    const __half2* Pb = reinterpret_cast<const __half2*>(g_P + (size_t)(b * Nn) * Nn);

    float ax = 0.0f, ay = 0.0f;
    #pragma unroll 4
    for (int q = 0; q < 256; q++) {
        float2 v = __half22float2(Pb[(size_t)(q0 + q) * (Nn / 2) + k2]);
        float w = iz[q];
        ax += v.x * w;
        ay += v.y * w;
    }
    atomicAdd(&g_w[b * Nn + 2 * k2],     ax);
    atomicAdd(&g_w[b * Nn + 2 * k2 + 1], ay);
}

// ---------------- kernel 6: out[b,h] = (1/N) sum_k w[b,k] V[b,k,h] ----------------
__global__ __launch_bounds__(256) void out_kernel(float* __restrict__ out) {
    const int b  = blockIdx.x;
    const int ks = blockIdx.y;
    const int h  = threadIdx.x;
    const float* Vb = g_V + (size_t)b * Nn * Hh;

    float acc = 0.0f;
    #pragma unroll 8
    for (int k = ks * 256; k < ks * 256 + 256; k++)
        acc += g_w[b * Nn + k] * Vb[(size_t)k * Hh + h];

    atomicAdd(&out[b * Hh + h], acc * (1.0f / Nn));
}

// ---------------- launch ----------------
extern "C" void kernel_launch(void* const* d_in, const int* in_sizes, int n_in,
                              void* d_out, int out_size) {
    const float* x  = (const float*)d_in[0];
    const float* Wq = (const float*)d_in[1];
    const float* bq = (const float*)d_in[2];
    const float* Wk = (const float*)d_in[3];
    const float* bk = (const float*)d_in[4];
    const float* Wv = (const float*)d_in[5];
    const float* bv = (const float*)d_in[6];
    float* out = (float*)d_out;

    cudaFuncSetAttribute(qkv_mma_kernel,
                         cudaFuncAttributeMaxDynamicSharedMemorySize, QKV_DYN_SMEM);
    cudaFuncSetAttribute(scores_fused_kernel,
                         cudaFuncAttributeMaxDynamicSharedMemorySize, SC_DYN_SMEM);

    zero_kernel<<<128, 256>>>(out);
    convert_x_kernel<<<(Bb * Nn * Dd / 2) / 256, 256>>>(x);
    transpose_w_kernel<<<dim3(8, 8, 3), dim3(32, 8)>>>(Wq, Wk, Wv);
    qkv_mma_kernel<<<dim3(Hh / 128, (Bb * Nn) / 128, 3), 256, QKV_DYN_SMEM>>>(bq, bk, bv);
    scores_fused_kernel<<<dim3(Nn / 256, Nn / 128, Bb), 256, SC_DYN_SMEM>>>();
    invz_kernel<<<128, 256>>>();
    colsum_kernel<<<dim3(Nn / 256, Nn / 256, Bb), 128>>>();
    out_kernel<<<dim3(Bb, 16), 256>>>(out);
}

// round 13
// speedup vs baseline: 6.6342x; 1.0449x over previous
#include <cuda_runtime.h>
#include <cuda_fp16.h>
#include <math.h>
#include <stdint.h>

#define Bb 8
#define Nn 4096
#define Dd 256
#define Hh 256

// ---------------- static device scratch (allocation-free) ----------------
__device__ __half g_xh[(size_t)Bb * Nn * Dd];            // 16.8 MB  x in fp16
__device__ __half g_Qh[(size_t)Bb * Nn * Hh];            // 16.8 MB  Q in fp16
__device__ __half g_Kh[(size_t)Bb * Nn * Hh];            // 16.8 MB  K in fp16
__device__ float  g_V[(size_t)Bb * Nn * Hh];             // 33.5 MB  V fp32
__device__ __half g_P[(size_t)Bb * Nn * Nn];             // 268 MB: P = exp(S) fp16
__device__ __half g_Wth[3 * Dd * Hh];                    // W^T fp16 for Q,K,V
__device__ float  g_z[Bb * Nn];                          // row sums Z
__device__ float  g_w[Bb * Nn];                          // column weights

// ================= helpers =================
__device__ __forceinline__ uint32_t smem_u32(const void* p) {
    uint32_t a;
    asm("{ .reg .u64 t; cvta.to.shared.u64 t, %1; cvt.u32.u64 %0, t; }" : "=r"(a) : "l"(p));
    return a;
}
__device__ __forceinline__ void cpasync16(uint32_t dst, const void* src) {
    asm volatile("cp.async.ca.shared.global [%0], [%1], 16;" :: "r"(dst), "l"(src));
}
#define CP_COMMIT() asm volatile("cp.async.commit_group;" ::: "memory")
#define CP_WAIT(N)  asm volatile("cp.async.wait_group %0;" :: "n"(N) : "memory")

__device__ __forceinline__ void ldm_x4(uint32_t& r0, uint32_t& r1, uint32_t& r2, uint32_t& r3,
                                       uint32_t addr) {
    asm volatile("ldmatrix.sync.aligned.m8n8.x4.shared.b16 {%0,%1,%2,%3}, [%4];"
                 : "=r"(r0), "=r"(r1), "=r"(r2), "=r"(r3) : "r"(addr));
}
// fp16 inputs, fp32 accumulate (QKV projection)
__device__ __forceinline__ void mma_f16f32(float* c,
                                           uint32_t a0, uint32_t a1, uint32_t a2, uint32_t a3,
                                           uint32_t b0, uint32_t b1) {
    asm volatile(
        "mma.sync.aligned.m16n8k16.row.col.f32.f16.f16.f32 "
        "{%0,%1,%2,%3}, {%4,%5,%6,%7}, {%8,%9}, {%0,%1,%2,%3};"
        : "+f"(c[0]), "+f"(c[1]), "+f"(c[2]), "+f"(c[3])
        : "r"(a0), "r"(a1), "r"(a2), "r"(a3), "r"(b0), "r"(b1));
}
// fp16 inputs, fp16 accumulate (scores)
__device__ __forceinline__ void mma_f16(uint32_t* c,
                                        uint32_t a0, uint32_t a1, uint32_t a2, uint32_t a3,
                                        uint32_t b0, uint32_t b1) {
    asm volatile(
        "mma.sync.aligned.m16n8k16.row.col.f16.f16.f16.f16 "
        "{%0,%1}, {%2,%3,%4,%5}, {%6,%7}, {%0,%1};"
        : "+r"(c[0]), "+r"(c[1])
        : "r"(a0), "r"(a1), "r"(a2), "r"(a3), "r"(b0), "r"(b1));
}
#define SW128(o) ((o) ^ (((o) >> 3) & 0x70u))

#define QKV_DYN_SMEM 65536    // 2 buffers x (A 16KB + B 16KB)
#define SC_DYN_SMEM  98304    // 2 buffers x (A 16KB + B 32KB)

// ---------------- kernel 0: x -> fp16 (+ zero accumulators) ----------------
__global__ __launch_bounds__(256) void convert_x_kernel(const float* __restrict__ x,
                                                        float* __restrict__ out) {
    int i = blockIdx.x * 256 + threadIdx.x;           // one float2 -> half2
    float2 v = reinterpret_cast<const float2*>(x)[i];
    reinterpret_cast<__half2*>(g_xh)[i] = __floats2half2_rn(v.x, v.y);
    if (i < Bb * Nn) { g_w[i] = 0.0f; g_z[i] = 0.0f; }
    if (i < Bb * Hh) out[i] = 0.0f;
}

// ---------------- kernel 1: W transpose -> fp16 ----------------
__global__ void transpose_w_kernel(const float* __restrict__ Wq,
                                   const float* __restrict__ Wk,
                                   const float* __restrict__ Wv) {
    const float* W = (blockIdx.z == 0) ? Wq : (blockIdx.z == 1) ? Wk : Wv;
    __half* Wt = g_Wth + blockIdx.z * (Dd * Hh);
    __shared__ float t[32][33];
    const int x0 = blockIdx.x * 32, y0 = blockIdx.y * 32;
    #pragma unroll
    for (int i = threadIdx.y; i < 32; i += 8)
        t[i][threadIdx.x] = W[(size_t)(y0 + i) * Hh + x0 + threadIdx.x];
    __syncthreads();
    #pragma unroll
    for (int i = threadIdx.y; i < 32; i += 8)
        Wt[(size_t)(x0 + i) * Dd + y0 + threadIdx.x] = __float2half(t[threadIdx.x][i]);
}

// ---------------- kernel 2: QKV projection, fp16 inputs / f32 acc ----------------
// CTA tile 128(r) x 128(h), K=256 in 4 chunks of k64. Warp tile 64x32. ldmatrix loads.
// grid: (Hh/128, (B*N)/128, 3)  block: 256
__global__ __launch_bounds__(256, 2) void qkv_mma_kernel(
    const float* __restrict__ bq, const float* __restrict__ bk, const float* __restrict__ bv)
{
    extern __shared__ float dynsm[];
    const uint32_t sb = smem_u32(dynsm);
    const int tid  = threadIdx.x;
    const int wid  = tid >> 5;
    const int lane = tid & 31;
    const int g = lane >> 2, t = lane & 3;
    const int wm = (wid & 1) * 64;
    const int wn = (wid >> 1) * 32;
    const int lr = tid >> 3;
    const int lc = tid & 7;

    const int z  = blockIdx.z;
    const float* bias = (z == 0) ? bq : (z == 1) ? bk : bv;
    const int r0 = blockIdx.y * 128;
    const int h0 = blockIdx.x * 128;

    const uint32_t stsOff = SW128((uint32_t)(lr * 128 + lc * 16));
    const __half* Aq = g_xh + (size_t)r0 * Dd + (size_t)lr * 256 + lc * 8;
    const __half* Bk = g_Wth + z * (Dd * Hh) + (size_t)h0 * Dd + (size_t)lr * 256 + lc * 8;

    // ldmatrix per-lane addressing
    const int quad = lane >> 3, rr = lane & 7;
    const uint32_t swzL = (uint32_t)rr << 4;
    const uint32_t aRowOff = (uint32_t)(wm + (quad & 1) * 8 + rr) * 128u;
    const uint32_t colSelA = (uint32_t)(quad >> 1) * 16u;
    const uint32_t bRowOff = (uint32_t)(wn + (quad >> 1) * 8 + rr) * 128u;
    const uint32_t colSelB = (uint32_t)(quad & 1) * 16u;

    float c[4][4][4];
    #pragma unroll
    for (int mt = 0; mt < 4; mt++)
        #pragma unroll
        for (int nt = 0; nt < 4; nt++)
            #pragma unroll
            for (int r = 0; r < 4; r++) c[mt][nt][r] = 0.0f;

    auto issue = [&](int ch, int buf) {
        const uint32_t ba = sb + (uint32_t)buf * 32768u;
        const __half* qa = Aq + ch * 64;
        const __half* ka = Bk + ch * 64;
        #pragma unroll
        for (int i = 0; i < 4; i++) {
            cpasync16(ba + stsOff + i * 4096u,          qa + (size_t)i * 32 * 256);
            cpasync16(ba + 16384u + stsOff + i * 4096u, ka + (size_t)i * 32 * 256);
        }
        CP_COMMIT();
    };
    auto compute = [&](int buf) {
        const uint32_t aB = sb + (uint32_t)buf * 32768u + aRowOff;
        const uint32_t bB = sb + (uint32_t)buf * 32768u + 16384u + bRowOff;
        #pragma unroll
        for (int ks = 0; ks < 4; ks++) {
            const uint32_t ctA = ((uint32_t)(ks * 32) + colSelA) ^ swzL;
            const uint32_t ctB = ((uint32_t)(ks * 32) + colSelB) ^ swzL;
            uint32_t b[4][2];
            #pragma unroll
            for (int np = 0; np < 2; np++)
                ldm_x4(b[2*np][0], b[2*np][1], b[2*np+1][0], b[2*np+1][1],
                       bB + np * 2048u + ctB);
            #pragma unroll
            for (int mt = 0; mt < 4; mt++) {
                uint32_t a0, a1, a2, a3;
                ldm_x4(a0, a1, a2, a3, aB + mt * 2048u + ctA);
                #pragma unroll
                for (int nt = 0; nt < 4; nt++)
                    mma_f16f32(c[mt][nt], a0, a1, a2, a3, b[nt][0], b[nt][1]);
            }
        }
    };

    issue(0, 0); issue(1, 1);
    #pragma unroll 1
    for (int ch = 0; ch < 4; ch++) {
        if (ch == 3) { CP_WAIT(0); } else { CP_WAIT(1); }
        __syncthreads();
        compute(ch & 1);
        __syncthreads();
        if (ch + 2 < 4) issue(ch + 2, ch & 1);
    }

    if (z == 2) {
        #pragma unroll
        for (int mt = 0; mt < 4; mt++) {
            const int row = r0 + wm + mt * 16 + g;
            #pragma unroll
            for (int nt = 0; nt < 4; nt++) {
                const int col = h0 + wn + nt * 8 + 2 * t;
                float2 bc = *reinterpret_cast<const float2*>(&bias[col]);
                float2 v0, v1;
                v0.x = c[mt][nt][0] + bc.x; v0.y = c[mt][nt][1] + bc.y;
                v1.x = c[mt][nt][2] + bc.x; v1.y = c[mt][nt][3] + bc.y;
                *reinterpret_cast<float2*>(&g_V[(size_t)row       * Hh + col]) = v0;
                *reinterpret_cast<float2*>(&g_V[(size_t)(row + 8) * Hh + col]) = v1;
            }
        }
    } else {
        __half* outh = (z == 0) ? g_Qh : g_Kh;
        #pragma unroll
        for (int mt = 0; mt < 4; mt++) {
            const int row = r0 + wm + mt * 16 + g;
            #pragma unroll
            for (int nt = 0; nt < 4; nt++) {
                const int col = h0 + wn + nt * 8 + 2 * t;
                float2 bc = *reinterpret_cast<const float2*>(&bias[col]);
                *reinterpret_cast<__half2*>(&outh[(size_t)row       * Hh + col]) =
                    __floats2half2_rn(c[mt][nt][0] + bc.x, c[mt][nt][1] + bc.y);
                *reinterpret_cast<__half2*>(&outh[(size_t)(row + 8) * Hh + col]) =
                    __floats2half2_rn(c[mt][nt][2] + bc.x, c[mt][nt][3] + bc.y);
            }
        }
    }
}

// ---------------- kernel 3: P = exp(Q K^T * scale), Z row-sums ----------------
// fp16 in, fp16 acc. CTA tile 128(q) x 256(k); warp tile 64x64; ldmatrix loads.
// grid: (N/256, N/128, B)  block: 256
__global__ __launch_bounds__(256, 2) void scores_fused_kernel() {
    extern __shared__ float dynsm[];
    __shared__ float rsum[128];
    const uint32_t sb = smem_u32(dynsm);
    const int tid  = threadIdx.x;
    const int wid  = tid >> 5;
    const int lane = tid & 31;
    const int g = lane >> 2, t = lane & 3;
    const int wm = (wid & 1) * 64;
    const int wn = (wid >> 1) * 64;
    const int lr = tid >> 3;
    const int lc = tid & 7;

    const int b  = blockIdx.z;
    const int q0 = blockIdx.y * 128;
    const int k0 = blockIdx.x * 256;

    const uint32_t stsOff = SW128((uint32_t)(lr * 128 + lc * 16));
    const __half* Aq = g_Qh + (size_t)(b * Nn + q0) * Hh + (size_t)lr * 256 + lc * 8;
    const __half* Bk = g_Kh + (size_t)(b * Nn + k0) * Hh + (size_t)lr * 256 + lc * 8;

    const int quad = lane >> 3, rr = lane & 7;
    const uint32_t swzL = (uint32_t)rr << 4;
    const uint32_t aRowOff = (uint32_t)(wm + (quad & 1) * 8 + rr) * 128u;
    const uint32_t colSelA = (uint32_t)(quad >> 1) * 16u;
    const uint32_t bRowOff = (uint32_t)(wn + (quad >> 1) * 8 + rr) * 128u;
    const uint32_t colSelB = (uint32_t)(quad & 1) * 16u;

    uint32_t c[4][8][2];   // f16x2 accumulators: 64 regs
    #pragma unroll
    for (int mt = 0; mt < 4; mt++)
        #pragma unroll
        for (int nt = 0; nt < 8; nt++) { c[mt][nt][0] = 0u; c[mt][nt][1] = 0u; }

    auto issue = [&](int ch, int buf) {
        const uint32_t ba = sb + (uint32_t)buf * 49152u;
        const __half* qa = Aq + ch * 64;
        const __half* ka = Bk + ch * 64;
        #pragma unroll
        for (int i = 0; i < 4; i++)
            cpasync16(ba + stsOff + i * 4096u, qa + (size_t)i * 32 * 256);
        #pragma unroll
        for (int i = 0; i < 8; i++)
            cpasync16(ba + 16384u + stsOff + i * 4096u, ka + (size_t)i * 32 * 256);
        CP_COMMIT();
    };
    auto compute = [&](int buf) {
        const uint32_t aB = sb + (uint32_t)buf * 49152u + aRowOff;
        const uint32_t bB = sb + (uint32_t)buf * 49152u + 16384u + bRowOff;
        #pragma unroll
        for (int ks = 0; ks < 4; ks++) {
            const uint32_t ctA = ((uint32_t)(ks * 32) + colSelA) ^ swzL;
            const uint32_t ctB = ((uint32_t)(ks * 32) + colSelB) ^ swzL;
            uint32_t b[8][2];
            #pragma unroll
            for (int np = 0; np < 4; np++)
                ldm_x4(b[2*np][0], b[2*np][1], b[2*np+1][0], b[2*np+1][1],
                       bB + np * 2048u + ctB);
            #pragma unroll
            for (int mt = 0; mt < 4; mt++) {
                uint32_t a0, a1, a2, a3;
                ldm_x4(a0, a1, a2, a3, aB + mt * 2048u + ctA);
                #pragma unroll
                for (int nt = 0; nt < 8; nt++)
                    mma_f16(c[mt][nt], a0, a1, a2, a3, b[nt][0], b[nt][1]);
            }
        }
    };

    issue(0, 0); issue(1, 1);
    #pragma unroll 1
    for (int ch = 0; ch < 4; ch++) {
        if (ch == 3) { CP_WAIT(0); } else { CP_WAIT(1); }
        __syncthreads();
        compute(ch & 1);
        __syncthreads();
        if (ch + 2 < 4) issue(ch + 2, ch & 1);
    }

    // ---- fused epilogue: exp, fp16 store, per-row Z partial sums ----
    if (tid < 128) rsum[tid] = 0.0f;
    __syncthreads();

    const float scale = 0.0625f;    // 1/sqrt(256)
    __half* Ph = g_P + (size_t)(b * Nn) * Nn;

    #pragma unroll
    for (int mt = 0; mt < 4; mt++) {
        const int row = wm + mt * 16 + g;
        float s0 = 0.0f, s1 = 0.0f;
        #pragma unroll
        for (int nt = 0; nt < 8; nt++) {
            const int col = k0 + wn + nt * 8 + 2 * t;
            float2 v0 = __half22float2(*reinterpret_cast<__half2*>(&c[mt][nt][0]));
            float2 v1 = __half22float2(*reinterpret_cast<__half2*>(&c[mt][nt][1]));
            float e0 = __expf(v0.x * scale);
            float e1 = __expf(v0.y * scale);
            float e2 = __expf(v1.x * scale);
            float e3 = __expf(v1.y * scale);
            s0 += e0 + e1;
            s1 += e2 + e3;
            *reinterpret_cast<__half2*>(&Ph[(size_t)(q0 + row)     * Nn + col]) =
                __floats2half2_rn(e0, e1);
            *reinterpret_cast<__half2*>(&Ph[(size_t)(q0 + row + 8) * Nn + col]) =
                __floats2half2_rn(e2, e3);
        }
        s0 += __shfl_xor_sync(0xFFFFFFFFu, s0, 1);
        s0 += __shfl_xor_sync(0xFFFFFFFFu, s0, 2);
        s1 += __shfl_xor_sync(0xFFFFFFFFu, s1, 1);
        s1 += __shfl_xor_sync(0xFFFFFFFFu, s1, 2);
        if (t == 0) {
            atomicAdd(&rsum[row],     s0);
            atomicAdd(&rsum[row + 8], s1);
        }
    }
    __syncthreads();
    if (tid < 128) atomicAdd(&g_z[b * Nn + q0 + tid], rsum[tid]);
}

// ---------------- kernel 4: w[b,k] = sum_q P[q,k] / Z[q]  (invZ fused) ----------------
__global__ __launch_bounds__(128) void colsum_kernel() {
    const int b  = blockIdx.z;
    const int k2 = blockIdx.x * 128 + threadIdx.x;
    const int q0 = blockIdx.y * 256;

    __shared__ float iz[256];
    if (threadIdx.x < 128) {
        iz[threadIdx.x]       = 1.0f / g_z[b * Nn + q0 + threadIdx.x];
        iz[threadIdx.x + 128] = 1.0f / g_z[b * Nn + q0 + 128 + threadIdx.x];
    }
    __syncthreads();

    const __half2* Pb = reinterpret_cast<const __half2*>(g_P + (size_t)(b * Nn) * Nn);

    float ax = 0.0f, ay = 0.0f;
    #pragma unroll 4
    for (int q = 0; q < 256; q++) {
        float2 v = __half22float2(Pb[(size_t)(q0 + q) * (Nn / 2) + k2]);
        float w = iz[q];
        ax += v.x * w;
        ay += v.y * w;
    }
    atomicAdd(&g_w[b * Nn + 2 * k2],     ax);
    atomicAdd(&g_w[b * Nn + 2 * k2 + 1], ay);
}

// ---------------- kernel 5: out[b,h] = (1/N) sum_k w[b,k] V[b,k,h] ----------------
__global__ __launch_bounds__(256) void out_kernel(float* __restrict__ out) {
    const int b  = blockIdx.x;
    const int ks = blockIdx.y;
    const int h  = threadIdx.x;
    const float* Vb = g_V + (size_t)b * Nn * Hh;

    float acc = 0.0f;
    #pragma unroll 8
    for (int k = ks * 256; k < ks * 256 + 256; k++)
        acc += g_w[b * Nn + k] * Vb[(size_t)k * Hh + h];

    atomicAdd(&out[b * Hh + h], acc * (1.0f / Nn));
}

// ---------------- launch ----------------
extern "C" void kernel_launch(void* const* d_in, const int* in_sizes, int n_in,
                              void* d_out, int out_size) {
    const float* x  = (const float*)d_in[0];
    const float* Wq = (const float*)d_in[1];
    const float* bq = (const float*)d_in[2];
    const float* Wk = (const float*)d_in[3];
    const float* bk = (const float*)d_in[4];
    const float* Wv = (const float*)d_in[5];
    const float* bv = (const float*)d_in[6];
    float* out = (float*)d_out;

    cudaFuncSetAttribute(qkv_mma_kernel,
                         cudaFuncAttributeMaxDynamicSharedMemorySize, QKV_DYN_SMEM);
    cudaFuncSetAttribute(scores_fused_kernel,
                         cudaFuncAttributeMaxDynamicSharedMemorySize, SC_DYN_SMEM);

    convert_x_kernel<<<(Bb * Nn * Dd / 2) / 256, 256>>>(x, out);
    transpose_w_kernel<<<dim3(8, 8, 3), dim3(32, 8)>>>(Wq, Wk, Wv);
    qkv_mma_kernel<<<dim3(Hh / 128, (Bb * Nn) / 128, 3), 256, QKV_DYN_SMEM>>>(bq, bk, bv);
    scores_fused_kernel<<<dim3(Nn / 256, Nn / 128, Bb), 256, SC_DYN_SMEM>>>();
    colsum_kernel<<<dim3(Nn / 256, Nn / 256, Bb), 128>>>();
    out_kernel<<<dim3(Bb, 16), 256>>>(out);
}